// round 3
// baseline (speedup 1.0000x reference)
#include <cuda_runtime.h>
#include <cuda_bf16.h>
#include <math.h>

// Problem constants
#define SEQ   2048
#define DIM   4096
#define NH    32
#define NKV   8
#define HD    128
#define KVDIM 1024   // NKV * HD

// ----------------------------------------------------------------------------
// Scratch (device-global: no allocations allowed anywhere)
// ----------------------------------------------------------------------------
__device__ float  g_Q[SEQ * DIM];
__device__ float  g_K[SEQ * KVDIM];
__device__ float  g_V[SEQ * KVDIM];
__device__ float  g_attn[SEQ * DIM];
__device__ float2 g_cs[SEQ * 64];

// bf16 split (hi/lo) scratch
__device__ __nv_bfloat16 g_xs_h[SEQ * DIM],     g_xs_l[SEQ * DIM];
__device__ __nv_bfloat16 g_wq_h[DIM * DIM],     g_wq_l[DIM * DIM];
__device__ __nv_bfloat16 g_wk_h[KVDIM * DIM],   g_wk_l[KVDIM * DIM];
__device__ __nv_bfloat16 g_wv_h[KVDIM * DIM],   g_wv_l[KVDIM * DIM];
__device__ __nv_bfloat16 g_wo_h[DIM * DIM],     g_wo_l[DIM * DIM];
__device__ __nv_bfloat16 g_Qh[SEQ * DIM],       g_Ql[SEQ * DIM];
__device__ __nv_bfloat16 g_Kh[SEQ * KVDIM],     g_Kl[SEQ * KVDIM];
__device__ __nv_bfloat16 g_Vh[SEQ * KVDIM],     g_Vl[SEQ * KVDIM];
__device__ __nv_bfloat16 g_ah[SEQ * DIM],       g_al[SEQ * DIM];

// ----------------------------------------------------------------------------
// Helpers
// ----------------------------------------------------------------------------
__device__ __forceinline__ unsigned pack2(__nv_bfloat16 a, __nv_bfloat16 b)
{
    return ((unsigned)__bfloat16_as_ushort(b) << 16) | (unsigned)__bfloat16_as_ushort(a);
}

__device__ __forceinline__ void bsplit(float x, __nv_bfloat16& h, __nv_bfloat16& l)
{
    h = __float2bfloat16(x);
    l = __float2bfloat16(x - __bfloat162float(h));
}

// D = A(row) * B(col) + D, bf16 in, fp32 accum
__device__ __forceinline__ void mma_bf16(float* c, const unsigned* a, const unsigned* b)
{
    asm volatile(
        "mma.sync.aligned.m16n8k16.row.col.f32.bf16.bf16.f32 "
        "{%0,%1,%2,%3}, {%4,%5,%6,%7}, {%8,%9}, {%0,%1,%2,%3};"
        : "+f"(c[0]), "+f"(c[1]), "+f"(c[2]), "+f"(c[3])
        : "r"(a[0]), "r"(a[1]), "r"(a[2]), "r"(a[3]), "r"(b[0]), "r"(b[1]));
}

__device__ __forceinline__ void ldsm_x2_t(unsigned& r0, unsigned& r1, unsigned addr)
{
    asm volatile("ldmatrix.sync.aligned.m8n8.x2.trans.shared.b16 {%0,%1}, [%2];"
                 : "=r"(r0), "=r"(r1) : "r"(addr));
}

// ----------------------------------------------------------------------------
// RoPE cos/sin table (double-precision angles)
// ----------------------------------------------------------------------------
__global__ void __launch_bounds__(256) rope_table_kernel()
{
    int idx = blockIdx.x * blockDim.x + threadIdx.x;
    if (idx >= SEQ * 64) return;
    int s = idx >> 6, i = idx & 63;
    double freq = exp(-(double)i / 64.0 * log(500000.0));
    double a = (double)s * freq;
    g_cs[idx] = make_float2((float)cos(a), (float)sin(a));
}

// ----------------------------------------------------------------------------
// Generic fp32 -> (bf16 hi, bf16 lo) split, float4-vectorized
// ----------------------------------------------------------------------------
__global__ void __launch_bounds__(256) split_kernel(const float* __restrict__ src,
                                                    __nv_bfloat16* __restrict__ hi,
                                                    __nv_bfloat16* __restrict__ lo,
                                                    int n4)
{
    int i = blockIdx.x * blockDim.x + threadIdx.x;
    if (i >= n4) return;
    float4 v = ((const float4*)src)[i];
    __nv_bfloat16 hx, hy, hz, hw, lx, ly, lz, lw;
    bsplit(v.x, hx, lx); bsplit(v.y, hy, ly);
    bsplit(v.z, hz, lz); bsplit(v.w, hw, lw);
    ((uint2*)hi)[i] = make_uint2(pack2(hx, hy), pack2(hz, hw));
    ((uint2*)lo)[i] = make_uint2(pack2(lx, ly), pack2(lz, lw));
}

// ----------------------------------------------------------------------------
// RoPE + optional scale + split: fp32 X -> bf16 hi/lo (same linear layout)
// ----------------------------------------------------------------------------
__global__ void __launch_bounds__(256) rope_split_kernel(const float* __restrict__ X,
                                                         __nv_bfloat16* __restrict__ hi,
                                                         __nv_bfloat16* __restrict__ lo,
                                                         int nheads, int rowstride, float scale)
{
    int idx = blockIdx.x * blockDim.x + threadIdx.x;
    int i  = idx & 63;
    int hs = idx >> 6;
    int h  = hs % nheads;
    int s  = hs / nheads;
    float2 cs = g_cs[(s << 6) + i];
    size_t off = (size_t)s * rowstride + h * HD + 2 * i;
    float2 v = *(const float2*)(X + off);
    float r0 = (v.x * cs.x - v.y * cs.y) * scale;
    float r1 = (v.x * cs.y + v.y * cs.x) * scale;
    __nv_bfloat16 h0, h1, l0, l1;
    bsplit(r0, h0, l0); bsplit(r1, h1, l1);
    *(unsigned*)(hi + off) = pack2(h0, h1);
    *(unsigned*)(lo + off) = pack2(l0, l1);
}

// ----------------------------------------------------------------------------
// Split-bf16 tensor-core GEMM: C[M,N] = A[M,K] * B[N,K]^T, ~fp32 accuracy.
// A, B pre-split into bf16 hi/lo arrays. Block 128x128, BK=16, 8 warps
// (2m x 4n), warp tile 64x32 (4 m16 x 4 n8), 3 MMAs per k16 per tile.
// Smem word stride 12 (8 data + 4 pad): fragment LDS (g*12 + c) mod 32 is a
// 32-permutation -> conflict-free.
// ----------------------------------------------------------------------------
#define GW 12

__global__ void __launch_bounds__(256) gemm_bf16s(const __nv_bfloat16* __restrict__ Ahg,
                                                  const __nv_bfloat16* __restrict__ Alg,
                                                  const __nv_bfloat16* __restrict__ Bhg,
                                                  const __nv_bfloat16* __restrict__ Blg,
                                                  float* __restrict__ C, int N, int K)
{
    __shared__ unsigned Ah[128 * GW], Al[128 * GW], Bh[128 * GW], Bl[128 * GW];

    const int t    = threadIdx.x;
    const int lane = t & 31;
    const int wid  = t >> 5;
    const int wm   = wid & 1;
    const int wn   = wid >> 1;
    const int m0   = blockIdx.y << 7;
    const int n0   = blockIdx.x << 7;
    const int g    = lane >> 2;
    const int c    = lane & 3;

    // Loader: 128 rows x 2 uint4 (16 bf16/row) per matrix part per k-tile
    const int lrow  = t >> 1;
    const int lhalf = t & 1;
    const size_t aoff = (size_t)(m0 + lrow) * K + lhalf * 8;
    const size_t boff = (size_t)(n0 + lrow) * K + lhalf * 8;
    const int soff = lrow * GW + lhalf * 4;

    float acc[4][4][4];
#pragma unroll
    for (int mt = 0; mt < 4; mt++)
#pragma unroll
        for (int nt = 0; nt < 4; nt++)
#pragma unroll
            for (int r = 0; r < 4; r++) acc[mt][nt][r] = 0.f;

    uint4 pah = *(const uint4*)(Ahg + aoff);
    uint4 pal = *(const uint4*)(Alg + aoff);
    uint4 pbh = *(const uint4*)(Bhg + boff);
    uint4 pbl = *(const uint4*)(Blg + boff);

    const unsigned* ApH = Ah + ((wm << 6) + g) * GW + c;
    const unsigned* ApL = Al + ((wm << 6) + g) * GW + c;
    const unsigned* BpH = Bh + ((wn << 5) + g) * GW + c;
    const unsigned* BpL = Bl + ((wn << 5) + g) * GW + c;

    const int ktiles = K >> 4;
    for (int kt = 0; kt < ktiles; kt++) {
        __syncthreads();
        *(uint4*)&Ah[soff] = pah;
        *(uint4*)&Al[soff] = pal;
        *(uint4*)&Bh[soff] = pbh;
        *(uint4*)&Bl[soff] = pbl;
        __syncthreads();

        if (kt + 1 < ktiles) {
            size_t ko = (size_t)(kt + 1) * 16;
            pah = *(const uint4*)(Ahg + aoff + ko);
            pal = *(const uint4*)(Alg + aoff + ko);
            pbh = *(const uint4*)(Bhg + boff + ko);
            pbl = *(const uint4*)(Blg + boff + ko);
        }

        unsigned ah[4][4], al[4][4];
#pragma unroll
        for (int mt = 0; mt < 4; mt++) {
            const unsigned* pH = ApH + mt * (16 * GW);
            const unsigned* pL = ApL + mt * (16 * GW);
            ah[mt][0] = pH[0]; ah[mt][1] = pH[8 * GW]; ah[mt][2] = pH[4]; ah[mt][3] = pH[8 * GW + 4];
            al[mt][0] = pL[0]; al[mt][1] = pL[8 * GW]; al[mt][2] = pL[4]; al[mt][3] = pL[8 * GW + 4];
        }
#pragma unroll
        for (int nt = 0; nt < 4; nt++) {
            const unsigned* pH = BpH + nt * (8 * GW);
            const unsigned* pL = BpL + nt * (8 * GW);
            unsigned bh[2] = { pH[0], pH[4] };
            unsigned bl[2] = { pL[0], pL[4] };
#pragma unroll
            for (int mt = 0; mt < 4; mt++) {
                mma_bf16(acc[mt][nt], ah[mt], bh);
                mma_bf16(acc[mt][nt], ah[mt], bl);
                mma_bf16(acc[mt][nt], al[mt], bh);
            }
        }
    }

    const int erow = m0 + (wm << 6) + g;
    const int ecol = n0 + (wn << 5) + (c << 1);
#pragma unroll
    for (int mt = 0; mt < 4; mt++) {
#pragma unroll
        for (int nt = 0; nt < 4; nt++) {
            float* p0 = C + (size_t)(erow + mt * 16) * N + ecol + nt * 8;
            float* p1 = p0 + 8 * N;
            *(float2*)p0 = make_float2(acc[mt][nt][0], acc[mt][nt][1]);
            *(float2*)p1 = make_float2(acc[mt][nt][2], acc[mt][nt][3]);
        }
    }
}

// ----------------------------------------------------------------------------
// Tensor-core flash attention, split-bf16 (3-MMA) for both QK^T and PV.
// Block = (qb: 128 q rows, h). 8 warps, warp w owns m rows [16w, 16w+16).
// Online softmax in registers; rows r0 = base+g, r1 = base+g+8 per thread,
// state replicated across each lane quartet via shfl.
// P is rebuilt in A-fragment layout from S C-fragments (register-only).
// V operand fetched via ldmatrix.x2.trans.
// Smem word stride 68: frag LDS (g*68+c) mod 32 = 4g+c, conflict-free.
// ----------------------------------------------------------------------------
#define AQW 68
#define ATT_SMEM_BYTES ((2 * 128 * AQW + 4 * 64 * AQW) * 4)

__global__ void __launch_bounds__(256) attn_tc()
{
    extern __shared__ unsigned smw[];
    unsigned* Qh = smw;
    unsigned* Ql = Qh + 128 * AQW;
    unsigned* Kh = Ql + 128 * AQW;
    unsigned* Kl = Kh + 64 * AQW;
    unsigned* Vh = Kl + 64 * AQW;
    unsigned* Vl = Vh + 64 * AQW;

    const int qb  = blockIdx.x;
    const int h   = blockIdx.y;
    const int kvh = h >> 2;
    const int t    = threadIdx.x;
    const int lane = t & 31;
    const int w    = t >> 5;
    const int g    = lane >> 2;
    const int c    = lane & 3;

    // Load Q tile (128 x 128 bf16, hi+lo): 2048 uint4 per part
    for (int e = t; e < 2048; e += 256) {
        int r = e >> 4, u = e & 15;
        size_t go = (size_t)(qb * 128 + r) * DIM + h * HD + u * 8;
        *(uint4*)&Qh[r * AQW + u * 4] = *(const uint4*)(g_Qh + go);
        *(uint4*)&Ql[r * AQW + u * 4] = *(const uint4*)(g_Ql + go);
    }

    float cO[16][4];
#pragma unroll
    for (int jo = 0; jo < 16; jo++)
#pragma unroll
        for (int r = 0; r < 4; r++) cO[jo][r] = 0.f;
    float m0 = -INFINITY, m1 = -INFINITY, l0 = 0.f, l1 = 0.f;

    const int grow0 = qb * 128 + w * 16 + g;   // r1 = grow0 + 8
    const int vrow  = lane & 15;

    const int ntiles = 2 * qb + 2;
    for (int kt = 0; kt < ntiles; kt++) {
        __syncthreads();   // previous tile fully consumed (and Q stored, iter 0)
        for (int e = t; e < 1024; e += 256) {
            int r = e >> 4, u = e & 15;
            size_t go = (size_t)(kt * 64 + r) * KVDIM + kvh * HD + u * 8;
            *(uint4*)&Kh[r * AQW + u * 4] = *(const uint4*)(g_Kh + go);
            *(uint4*)&Kl[r * AQW + u * 4] = *(const uint4*)(g_Kl + go);
            *(uint4*)&Vh[r * AQW + u * 4] = *(const uint4*)(g_Vh + go);
            *(uint4*)&Vl[r * AQW + u * 4] = *(const uint4*)(g_Vl + go);
        }
        __syncthreads();

        if (kt * 64 <= qb * 128 + w * 16 + 15) {   // warp-tile intersects causal region
            // ---- S = Q K^T ----
            float cS[8][4];
#pragma unroll
            for (int j = 0; j < 8; j++)
#pragma unroll
                for (int r = 0; r < 4; r++) cS[j][r] = 0.f;

#pragma unroll
            for (int kk = 0; kk < 8; kk++) {
                const unsigned* qpH = Qh + (w * 16 + g) * AQW + kk * 8 + c;
                const unsigned* qpL = Ql + (w * 16 + g) * AQW + kk * 8 + c;
                unsigned qah[4] = { qpH[0], qpH[8 * AQW], qpH[4], qpH[8 * AQW + 4] };
                unsigned qal[4] = { qpL[0], qpL[8 * AQW], qpL[4], qpL[8 * AQW + 4] };
#pragma unroll
                for (int j = 0; j < 8; j++) {
                    const unsigned* kpH = Kh + (j * 8 + g) * AQW + kk * 8 + c;
                    const unsigned* kpL = Kl + (j * 8 + g) * AQW + kk * 8 + c;
                    unsigned bh[2] = { kpH[0], kpH[4] };
                    unsigned bl[2] = { kpL[0], kpL[4] };
                    mma_bf16(cS[j], qah, bh);
                    mma_bf16(cS[j], qah, bl);
                    mma_bf16(cS[j], qal, bh);
                }
            }

            // ---- causal mask ----
            if (kt * 64 + 63 > grow0) {
#pragma unroll
                for (int j = 0; j < 8; j++) {
                    int col = kt * 64 + j * 8 + 2 * c;
                    if (col     > grow0)     cS[j][0] = -INFINITY;
                    if (col + 1 > grow0)     cS[j][1] = -INFINITY;
                    if (col     > grow0 + 8) cS[j][2] = -INFINITY;
                    if (col + 1 > grow0 + 8) cS[j][3] = -INFINITY;
                }
            }

            // ---- online softmax ----
            float mx0 = -INFINITY, mx1 = -INFINITY;
#pragma unroll
            for (int j = 0; j < 8; j++) {
                mx0 = fmaxf(mx0, fmaxf(cS[j][0], cS[j][1]));
                mx1 = fmaxf(mx1, fmaxf(cS[j][2], cS[j][3]));
            }
            mx0 = fmaxf(mx0, __shfl_xor_sync(0xffffffffu, mx0, 1));
            mx0 = fmaxf(mx0, __shfl_xor_sync(0xffffffffu, mx0, 2));
            mx1 = fmaxf(mx1, __shfl_xor_sync(0xffffffffu, mx1, 1));
            mx1 = fmaxf(mx1, __shfl_xor_sync(0xffffffffu, mx1, 2));
            float mn0 = fmaxf(m0, mx0), mn1 = fmaxf(m1, mx1);
            float co0 = __expf(m0 - mn0), co1 = __expf(m1 - mn1);
            m0 = mn0; m1 = mn1;

            unsigned pAh[8], pAl[8], pBh[8], pBl[8];
            float s0 = 0.f, s1 = 0.f;
#pragma unroll
            for (int j = 0; j < 8; j++) {
                float p0 = __expf(cS[j][0] - mn0);
                float p1 = __expf(cS[j][1] - mn0);
                float p2 = __expf(cS[j][2] - mn1);
                float p3 = __expf(cS[j][3] - mn1);
                s0 += p0 + p1;
                s1 += p2 + p3;
                __nv_bfloat16 h0, h1, h2, h3, q0, q1, q2, q3;
                bsplit(p0, h0, q0); bsplit(p1, h1, q1);
                bsplit(p2, h2, q2); bsplit(p3, h3, q3);
                pAh[j] = pack2(h0, h1); pAl[j] = pack2(q0, q1);
                pBh[j] = pack2(h2, h3); pBl[j] = pack2(q2, q3);
            }
            s0 += __shfl_xor_sync(0xffffffffu, s0, 1);
            s0 += __shfl_xor_sync(0xffffffffu, s0, 2);
            s1 += __shfl_xor_sync(0xffffffffu, s1, 1);
            s1 += __shfl_xor_sync(0xffffffffu, s1, 2);
            l0 = l0 * co0 + s0;
            l1 = l1 * co1 + s1;
#pragma unroll
            for (int jo = 0; jo < 16; jo++) {
                cO[jo][0] *= co0; cO[jo][1] *= co0;
                cO[jo][2] *= co1; cO[jo][3] *= co1;
            }

            // ---- O += P V ----
#pragma unroll
            for (int tt = 0; tt < 4; tt++) {
                unsigned ah[4] = { pAh[2 * tt], pBh[2 * tt], pAh[2 * tt + 1], pBh[2 * tt + 1] };
                unsigned al[4] = { pAl[2 * tt], pBl[2 * tt], pAl[2 * tt + 1], pBl[2 * tt + 1] };
                unsigned baseH = (unsigned)__cvta_generic_to_shared(Vh + (tt * 16 + vrow) * AQW);
                unsigned baseL = (unsigned)__cvta_generic_to_shared(Vl + (tt * 16 + vrow) * AQW);
#pragma unroll
                for (int jo = 0; jo < 16; jo++) {
                    unsigned vh0, vh1, vl0, vl1;
                    ldsm_x2_t(vh0, vh1, baseH + jo * 16);
                    ldsm_x2_t(vl0, vl1, baseL + jo * 16);
                    unsigned bh[2] = { vh0, vh1 };
                    unsigned bl[2] = { vl0, vl1 };
                    mma_bf16(cO[jo], ah, bh);
                    mma_bf16(cO[jo], ah, bl);
                    mma_bf16(cO[jo], al, bh);
                }
            }
        }
    }

    // ---- normalize + write ----
    float i0 = 1.f / l0, i1 = 1.f / l1;
#pragma unroll
    for (int jo = 0; jo < 16; jo++) {
        size_t o0 = (size_t)grow0 * DIM + h * HD + jo * 8 + 2 * c;
        *(float2*)&g_attn[o0]           = make_float2(cO[jo][0] * i0, cO[jo][1] * i0);
        *(float2*)&g_attn[o0 + 8 * DIM] = make_float2(cO[jo][2] * i1, cO[jo][3] * i1);
    }
}

// ----------------------------------------------------------------------------
// Launch
// ----------------------------------------------------------------------------
extern "C" void kernel_launch(void* const* d_in, const int* in_sizes, int n_in,
                              void* d_out, int out_size)
{
    const float* x  = (const float*)d_in[0];
    const float* wq = (const float*)d_in[1];
    const float* wk = (const float*)d_in[2];
    const float* wv = (const float*)d_in[3];
    const float* wo = (const float*)d_in[4];
    float* out = (float*)d_out;

    float *Q, *K, *V, *attn;
    __nv_bfloat16 *xsh, *xsl, *wqh, *wql, *wkh, *wkl, *wvh, *wvl, *woh, *wol;
    __nv_bfloat16 *Qhp, *Qlp, *Khp, *Klp, *Vhp, *Vlp, *ahp, *alp;
    cudaGetSymbolAddress((void**)&Q,    g_Q);
    cudaGetSymbolAddress((void**)&K,    g_K);
    cudaGetSymbolAddress((void**)&V,    g_V);
    cudaGetSymbolAddress((void**)&attn, g_attn);
    cudaGetSymbolAddress((void**)&xsh,  g_xs_h); cudaGetSymbolAddress((void**)&xsl, g_xs_l);
    cudaGetSymbolAddress((void**)&wqh,  g_wq_h); cudaGetSymbolAddress((void**)&wql, g_wq_l);
    cudaGetSymbolAddress((void**)&wkh,  g_wk_h); cudaGetSymbolAddress((void**)&wkl, g_wk_l);
    cudaGetSymbolAddress((void**)&wvh,  g_wv_h); cudaGetSymbolAddress((void**)&wvl, g_wv_l);
    cudaGetSymbolAddress((void**)&woh,  g_wo_h); cudaGetSymbolAddress((void**)&wol, g_wo_l);
    cudaGetSymbolAddress((void**)&Qhp,  g_Qh);   cudaGetSymbolAddress((void**)&Qlp, g_Ql);
    cudaGetSymbolAddress((void**)&Khp,  g_Kh);   cudaGetSymbolAddress((void**)&Klp, g_Kl);
    cudaGetSymbolAddress((void**)&Vhp,  g_Vh);   cudaGetSymbolAddress((void**)&Vlp, g_Vl);
    cudaGetSymbolAddress((void**)&ahp,  g_ah);   cudaGetSymbolAddress((void**)&alp, g_al);

    cudaFuncSetAttribute(attn_tc, cudaFuncAttributeMaxDynamicSharedMemorySize,
                         ATT_SMEM_BYTES);

    const float scale = 0.08838834764831845f;  // 1/sqrt(128)

    rope_table_kernel<<<SEQ * 64 / 256, 256>>>();

    split_kernel<<<(SEQ * DIM / 4) / 256, 256>>>(x,  xsh, xsl, SEQ * DIM / 4);
    split_kernel<<<(DIM * DIM / 4) / 256, 256>>>(wq, wqh, wql, DIM * DIM / 4);
    split_kernel<<<(KVDIM * DIM / 4) / 256, 256>>>(wk, wkh, wkl, KVDIM * DIM / 4);
    split_kernel<<<(KVDIM * DIM / 4) / 256, 256>>>(wv, wvh, wvl, KVDIM * DIM / 4);
    split_kernel<<<(DIM * DIM / 4) / 256, 256>>>(wo, woh, wol, DIM * DIM / 4);

    gemm_bf16s<<<dim3(DIM / 128,   SEQ / 128), 256>>>(xsh, xsl, wqh, wql, Q, DIM,   DIM);
    gemm_bf16s<<<dim3(KVDIM / 128, SEQ / 128), 256>>>(xsh, xsl, wkh, wkl, K, KVDIM, DIM);
    gemm_bf16s<<<dim3(KVDIM / 128, SEQ / 128), 256>>>(xsh, xsl, wvh, wvl, V, KVDIM, DIM);

    rope_split_kernel<<<SEQ * NH  * 64 / 256, 256>>>(Q, Qhp, Qlp, NH,  DIM,   scale);
    rope_split_kernel<<<SEQ * NKV * 64 / 256, 256>>>(K, Khp, Klp, NKV, KVDIM, 1.f);
    split_kernel<<<(SEQ * KVDIM / 4) / 256, 256>>>(V, Vhp, Vlp, SEQ * KVDIM / 4);

    attn_tc<<<dim3(SEQ / 128, NH), 256, ATT_SMEM_BYTES>>>();

    split_kernel<<<(SEQ * DIM / 4) / 256, 256>>>(attn, ahp, alp, SEQ * DIM / 4);

    gemm_bf16s<<<dim3(DIM / 128, SEQ / 128), 256>>>(ahp, alp, woh, wol, out, DIM, DIM);
}

// round 4
// speedup vs baseline: 1.1550x; 1.1550x over previous
#include <cuda_runtime.h>
#include <cuda_bf16.h>
#include <math.h>

// Problem constants
#define SEQ   2048
#define DIM   4096
#define NH    32
#define NKV   8
#define HD    128
#define KVDIM 1024   // NKV * HD

// ----------------------------------------------------------------------------
// Scratch (device-global: no allocations allowed anywhere)
// ----------------------------------------------------------------------------
__device__ float  g_Q[SEQ * DIM];
__device__ float  g_K[SEQ * KVDIM];
__device__ float  g_V[SEQ * KVDIM];
__device__ float  g_attn[SEQ * DIM];
__device__ float2 g_cs[SEQ * 64];

// bf16 split (hi/lo) scratch
__device__ __nv_bfloat16 g_xs_h[SEQ * DIM],     g_xs_l[SEQ * DIM];
__device__ __nv_bfloat16 g_wq_h[DIM * DIM],     g_wq_l[DIM * DIM];
__device__ __nv_bfloat16 g_wk_h[KVDIM * DIM],   g_wk_l[KVDIM * DIM];
__device__ __nv_bfloat16 g_wv_h[KVDIM * DIM],   g_wv_l[KVDIM * DIM];
__device__ __nv_bfloat16 g_wo_h[DIM * DIM],     g_wo_l[DIM * DIM];
__device__ __nv_bfloat16 g_Qh[SEQ * DIM],       g_Ql[SEQ * DIM];
__device__ __nv_bfloat16 g_Kh[SEQ * KVDIM],     g_Kl[SEQ * KVDIM];
__device__ __nv_bfloat16 g_Vh[SEQ * KVDIM],     g_Vl[SEQ * KVDIM];
__device__ __nv_bfloat16 g_ah[SEQ * DIM],       g_al[SEQ * DIM];

// ----------------------------------------------------------------------------
// Helpers
// ----------------------------------------------------------------------------
__device__ __forceinline__ unsigned pack2(__nv_bfloat16 a, __nv_bfloat16 b)
{
    return ((unsigned)__bfloat16_as_ushort(b) << 16) | (unsigned)__bfloat16_as_ushort(a);
}

__device__ __forceinline__ void bsplit(float x, __nv_bfloat16& h, __nv_bfloat16& l)
{
    h = __float2bfloat16(x);
    l = __float2bfloat16(x - __bfloat162float(h));
}

__device__ __forceinline__ void mma_bf16(float* c, const unsigned* a, const unsigned* b)
{
    asm volatile(
        "mma.sync.aligned.m16n8k16.row.col.f32.bf16.bf16.f32 "
        "{%0,%1,%2,%3}, {%4,%5,%6,%7}, {%8,%9}, {%0,%1,%2,%3};"
        : "+f"(c[0]), "+f"(c[1]), "+f"(c[2]), "+f"(c[3])
        : "r"(a[0]), "r"(a[1]), "r"(a[2]), "r"(a[3]), "r"(b[0]), "r"(b[1]));
}

__device__ __forceinline__ void ldsm_x2_t(unsigned& r0, unsigned& r1, unsigned addr)
{
    asm volatile("ldmatrix.sync.aligned.m8n8.x2.trans.shared.b16 {%0,%1}, [%2];"
                 : "=r"(r0), "=r"(r1) : "r"(addr));
}

__device__ __forceinline__ void ldsm_x4(unsigned& r0, unsigned& r1, unsigned& r2,
                                        unsigned& r3, unsigned addr)
{
    asm volatile("ldmatrix.sync.aligned.m8n8.x4.shared.b16 {%0,%1,%2,%3}, [%4];"
                 : "=r"(r0), "=r"(r1), "=r"(r2), "=r"(r3) : "r"(addr));
}

#define CP_ASYNC16(dst, src) \
    asm volatile("cp.async.cg.shared.global [%0], [%1], 16;" :: "r"(dst), "l"(src))
#define CP_COMMIT() asm volatile("cp.async.commit_group;")
#define CP_WAIT(n)  asm volatile("cp.async.wait_group %0;" :: "n"(n))

// ----------------------------------------------------------------------------
// RoPE cos/sin table (double-precision angles)
// ----------------------------------------------------------------------------
__global__ void __launch_bounds__(256) rope_table_kernel()
{
    int idx = blockIdx.x * blockDim.x + threadIdx.x;
    if (idx >= SEQ * 64) return;
    int s = idx >> 6, i = idx & 63;
    double freq = exp(-(double)i / 64.0 * log(500000.0));
    double a = (double)s * freq;
    g_cs[idx] = make_float2((float)cos(a), (float)sin(a));
}

// ----------------------------------------------------------------------------
// Generic fp32 -> (bf16 hi, bf16 lo) split
// ----------------------------------------------------------------------------
__global__ void __launch_bounds__(256) split_kernel(const float* __restrict__ src,
                                                    __nv_bfloat16* __restrict__ hi,
                                                    __nv_bfloat16* __restrict__ lo,
                                                    int n4)
{
    int i = blockIdx.x * blockDim.x + threadIdx.x;
    if (i >= n4) return;
    float4 v = ((const float4*)src)[i];
    __nv_bfloat16 hx, hy, hz, hw, lx, ly, lz, lw;
    bsplit(v.x, hx, lx); bsplit(v.y, hy, ly);
    bsplit(v.z, hz, lz); bsplit(v.w, hw, lw);
    ((uint2*)hi)[i] = make_uint2(pack2(hx, hy), pack2(hz, hw));
    ((uint2*)lo)[i] = make_uint2(pack2(lx, ly), pack2(lz, lw));
}

// ----------------------------------------------------------------------------
// RoPE + optional scale + split
// ----------------------------------------------------------------------------
__global__ void __launch_bounds__(256) rope_split_kernel(const float* __restrict__ X,
                                                         __nv_bfloat16* __restrict__ hi,
                                                         __nv_bfloat16* __restrict__ lo,
                                                         int nheads, int rowstride, float scale)
{
    int idx = blockIdx.x * blockDim.x + threadIdx.x;
    int i  = idx & 63;
    int hs = idx >> 6;
    int h  = hs % nheads;
    int s  = hs / nheads;
    float2 cs = g_cs[(s << 6) + i];
    size_t off = (size_t)s * rowstride + h * HD + 2 * i;
    float2 v = *(const float2*)(X + off);
    float r0 = (v.x * cs.x - v.y * cs.y) * scale;
    float r1 = (v.x * cs.y + v.y * cs.x) * scale;
    __nv_bfloat16 h0, h1, l0, l1;
    bsplit(r0, h0, l0); bsplit(r1, h1, l1);
    *(unsigned*)(hi + off) = pack2(h0, h1);
    *(unsigned*)(lo + off) = pack2(l0, l1);
}

// ----------------------------------------------------------------------------
// Split-bf16 tensor-core GEMM v2: C[M,N] = A[M,K]*B[N,K]^T, ~fp32 accuracy.
// Block 128x128, BK=32, 3-stage cp.async pipeline, ldmatrix.x4 fragments,
// 2 CTAs/SM. Smem row = 144B: [oct0 hi|oct0 lo|oct1 hi|...|oct3 lo|pad16].
// 144B = 36 words: ldmatrix phase rows r..r+7 hit banks 4r mod 32, distinct.
// ----------------------------------------------------------------------------
#define GSTRIDE 144
#define GTILEB  (128 * GSTRIDE)        // 18432 B per matrix per stage
#define GSTAGEB (2 * GTILEB)           // A + B
#define GSTAGES 3
#define GEMM_SMEM (GSTAGES * GSTAGEB)  // 110592 B

__global__ void __launch_bounds__(256, 2) gemm_bf16s(const __nv_bfloat16* __restrict__ Ahg,
                                                     const __nv_bfloat16* __restrict__ Alg,
                                                     const __nv_bfloat16* __restrict__ Bhg,
                                                     const __nv_bfloat16* __restrict__ Blg,
                                                     float* __restrict__ C, int N, int K)
{
    extern __shared__ char gsm[];
    const unsigned smem_u32 = (unsigned)__cvta_generic_to_shared(gsm);

    const int t    = threadIdx.x;
    const int lane = t & 31;
    const int wid  = t >> 5;
    const int wm   = wid & 1;
    const int wn   = wid >> 1;
    const int m0   = blockIdx.y << 7;
    const int n0   = blockIdx.x << 7;
    const int g    = lane >> 2;
    const int c    = lane & 3;

    // Loader mapping: row block arow=t>>3 (+32i, i=0..3), sub=t&7 -> (oct, part)
    const int arow = t >> 3;
    const int oct  = (t & 7) >> 1;
    const int part = t & 1;
    const __nv_bfloat16* srcA0 = (part ? Alg : Ahg) + (size_t)(m0 + arow) * K + oct * 8;
    const __nv_bfloat16* srcB0 = (part ? Blg : Bhg) + (size_t)(n0 + arow) * K + oct * 8;
    const unsigned dstA0 = arow * GSTRIDE + oct * 32 + part * 16;
    const unsigned dstB0 = dstA0 + GTILEB;

    // ldmatrix base offsets
    // A x4: matrices = [m+0..7 klo][m+8..15 klo][m+0..7 khi][m+8..15 khi]
    const unsigned aoffs = ((wm << 6) + (lane & 7) + ((lane >> 3) & 1) * 8) * GSTRIDE
                         + (lane >> 4) * 32;
    // B x4: matrices = [n+0..7 klo][n+0..7 khi][n+8..15 klo][n+8..15 khi]
    const unsigned boffs = GTILEB
                         + ((wn << 5) + (lane & 7) + (lane >> 4) * 8) * GSTRIDE
                         + ((lane >> 3) & 1) * 32;

    float acc[4][4][4];
#pragma unroll
    for (int mt = 0; mt < 4; mt++)
#pragma unroll
        for (int nt = 0; nt < 4; nt++)
#pragma unroll
            for (int r = 0; r < 4; r++) acc[mt][nt][r] = 0.f;

    const int nkt = K >> 5;   // BK = 32

    // cp.async issue for k-tile kt into stage s
    auto issue = [&](int s, int kt) {
        const __nv_bfloat16* sa = srcA0 + kt * 32;
        const __nv_bfloat16* sb = srcB0 + kt * 32;
        unsigned da = smem_u32 + s * GSTAGEB + dstA0;
        unsigned db = smem_u32 + s * GSTAGEB + dstB0;
#pragma unroll
        for (int i = 0; i < 4; i++)
            CP_ASYNC16(da + i * 32 * GSTRIDE, sa + (size_t)i * 32 * K);
#pragma unroll
        for (int i = 0; i < 4; i++)
            CP_ASYNC16(db + i * 32 * GSTRIDE, sb + (size_t)i * 32 * K);
        CP_COMMIT();
    };

    issue(0, 0);
    if (nkt > 1) issue(1, 1);

    for (int kt = 0; kt < nkt; kt++) {
        if (kt + 1 < nkt) { CP_WAIT(1); } else { CP_WAIT(0); }
        __syncthreads();
        if (kt + 2 < nkt) issue((kt + 2) % 3, kt + 2);

        const unsigned sa = smem_u32 + (kt % 3) * GSTAGEB + aoffs;
        const unsigned sb = smem_u32 + (kt % 3) * GSTAGEB + boffs;
#pragma unroll
        for (int kh = 0; kh < 2; kh++) {
            unsigned bh[4][2], bl[4][2];
#pragma unroll
            for (int q = 0; q < 2; q++) {
                unsigned base = sb + q * (16 * GSTRIDE) + kh * 64;
                ldsm_x4(bh[2 * q][0], bh[2 * q][1], bh[2 * q + 1][0], bh[2 * q + 1][1], base);
                ldsm_x4(bl[2 * q][0], bl[2 * q][1], bl[2 * q + 1][0], bl[2 * q + 1][1], base + 16);
            }
#pragma unroll
            for (int mt = 0; mt < 4; mt++) {
                unsigned ah[4], al[4];
                unsigned base = sa + mt * (16 * GSTRIDE) + kh * 64;
                ldsm_x4(ah[0], ah[1], ah[2], ah[3], base);
                ldsm_x4(al[0], al[1], al[2], al[3], base + 16);
#pragma unroll
                for (int nt = 0; nt < 4; nt++) {
                    mma_bf16(acc[mt][nt], ah, bh[nt]);
                    mma_bf16(acc[mt][nt], ah, bl[nt]);
                    mma_bf16(acc[mt][nt], al, bh[nt]);
                }
            }
        }
        __syncthreads();
    }

    const int erow = m0 + (wm << 6) + g;
    const int ecol = n0 + (wn << 5) + (c << 1);
#pragma unroll
    for (int mt = 0; mt < 4; mt++) {
#pragma unroll
        for (int nt = 0; nt < 4; nt++) {
            float* p0 = C + (size_t)(erow + mt * 16) * N + ecol + nt * 8;
            float* p1 = p0 + 8 * N;
            *(float2*)p0 = make_float2(acc[mt][nt][0], acc[mt][nt][1]);
            *(float2*)p1 = make_float2(acc[mt][nt][2], acc[mt][nt][3]);
        }
    }
}

// ----------------------------------------------------------------------------
// Tensor-core flash attention, split-bf16 (3-MMA) — unchanged from round 3
// (fragment layouts validated at rel_err 7.1e-5).
// ----------------------------------------------------------------------------
#define AQW 68
#define ATT_SMEM_BYTES ((2 * 128 * AQW + 4 * 64 * AQW) * 4)

__global__ void __launch_bounds__(256) attn_tc()
{
    extern __shared__ unsigned smw[];
    unsigned* Qh = smw;
    unsigned* Ql = Qh + 128 * AQW;
    unsigned* Kh = Ql + 128 * AQW;
    unsigned* Kl = Kh + 64 * AQW;
    unsigned* Vh = Kl + 64 * AQW;
    unsigned* Vl = Vh + 64 * AQW;

    const int qb  = blockIdx.x;
    const int h   = blockIdx.y;
    const int kvh = h >> 2;
    const int t    = threadIdx.x;
    const int lane = t & 31;
    const int w    = t >> 5;
    const int g    = lane >> 2;
    const int c    = lane & 3;

    for (int e = t; e < 2048; e += 256) {
        int r = e >> 4, u = e & 15;
        size_t go = (size_t)(qb * 128 + r) * DIM + h * HD + u * 8;
        *(uint4*)&Qh[r * AQW + u * 4] = *(const uint4*)(g_Qh + go);
        *(uint4*)&Ql[r * AQW + u * 4] = *(const uint4*)(g_Ql + go);
    }

    float cO[16][4];
#pragma unroll
    for (int jo = 0; jo < 16; jo++)
#pragma unroll
        for (int r = 0; r < 4; r++) cO[jo][r] = 0.f;
    float m0 = -INFINITY, m1 = -INFINITY, l0 = 0.f, l1 = 0.f;

    const int grow0 = qb * 128 + w * 16 + g;
    const int vrow  = lane & 15;

    const int ntiles = 2 * qb + 2;
    for (int kt = 0; kt < ntiles; kt++) {
        __syncthreads();
        for (int e = t; e < 1024; e += 256) {
            int r = e >> 4, u = e & 15;
            size_t go = (size_t)(kt * 64 + r) * KVDIM + kvh * HD + u * 8;
            *(uint4*)&Kh[r * AQW + u * 4] = *(const uint4*)(g_Kh + go);
            *(uint4*)&Kl[r * AQW + u * 4] = *(const uint4*)(g_Kl + go);
            *(uint4*)&Vh[r * AQW + u * 4] = *(const uint4*)(g_Vh + go);
            *(uint4*)&Vl[r * AQW + u * 4] = *(const uint4*)(g_Vl + go);
        }
        __syncthreads();

        if (kt * 64 <= qb * 128 + w * 16 + 15) {
            float cS[8][4];
#pragma unroll
            for (int j = 0; j < 8; j++)
#pragma unroll
                for (int r = 0; r < 4; r++) cS[j][r] = 0.f;

#pragma unroll
            for (int kk = 0; kk < 8; kk++) {
                const unsigned* qpH = Qh + (w * 16 + g) * AQW + kk * 8 + c;
                const unsigned* qpL = Ql + (w * 16 + g) * AQW + kk * 8 + c;
                unsigned qah[4] = { qpH[0], qpH[8 * AQW], qpH[4], qpH[8 * AQW + 4] };
                unsigned qal[4] = { qpL[0], qpL[8 * AQW], qpL[4], qpL[8 * AQW + 4] };
#pragma unroll
                for (int j = 0; j < 8; j++) {
                    const unsigned* kpH = Kh + (j * 8 + g) * AQW + kk * 8 + c;
                    const unsigned* kpL = Kl + (j * 8 + g) * AQW + kk * 8 + c;
                    unsigned bh[2] = { kpH[0], kpH[4] };
                    unsigned bl[2] = { kpL[0], kpL[4] };
                    mma_bf16(cS[j], qah, bh);
                    mma_bf16(cS[j], qah, bl);
                    mma_bf16(cS[j], qal, bh);
                }
            }

            if (kt * 64 + 63 > grow0) {
#pragma unroll
                for (int j = 0; j < 8; j++) {
                    int col = kt * 64 + j * 8 + 2 * c;
                    if (col     > grow0)     cS[j][0] = -INFINITY;
                    if (col + 1 > grow0)     cS[j][1] = -INFINITY;
                    if (col     > grow0 + 8) cS[j][2] = -INFINITY;
                    if (col + 1 > grow0 + 8) cS[j][3] = -INFINITY;
                }
            }

            float mx0 = -INFINITY, mx1 = -INFINITY;
#pragma unroll
            for (int j = 0; j < 8; j++) {
                mx0 = fmaxf(mx0, fmaxf(cS[j][0], cS[j][1]));
                mx1 = fmaxf(mx1, fmaxf(cS[j][2], cS[j][3]));
            }
            mx0 = fmaxf(mx0, __shfl_xor_sync(0xffffffffu, mx0, 1));
            mx0 = fmaxf(mx0, __shfl_xor_sync(0xffffffffu, mx0, 2));
            mx1 = fmaxf(mx1, __shfl_xor_sync(0xffffffffu, mx1, 1));
            mx1 = fmaxf(mx1, __shfl_xor_sync(0xffffffffu, mx1, 2));
            float mn0 = fmaxf(m0, mx0), mn1 = fmaxf(m1, mx1);
            float co0 = __expf(m0 - mn0), co1 = __expf(m1 - mn1);
            m0 = mn0; m1 = mn1;

            unsigned pAh[8], pAl[8], pBh[8], pBl[8];
            float s0 = 0.f, s1 = 0.f;
#pragma unroll
            for (int j = 0; j < 8; j++) {
                float p0 = __expf(cS[j][0] - mn0);
                float p1 = __expf(cS[j][1] - mn0);
                float p2 = __expf(cS[j][2] - mn1);
                float p3 = __expf(cS[j][3] - mn1);
                s0 += p0 + p1;
                s1 += p2 + p3;
                __nv_bfloat16 h0, h1, h2, h3, q0, q1, q2, q3;
                bsplit(p0, h0, q0); bsplit(p1, h1, q1);
                bsplit(p2, h2, q2); bsplit(p3, h3, q3);
                pAh[j] = pack2(h0, h1); pAl[j] = pack2(q0, q1);
                pBh[j] = pack2(h2, h3); pBl[j] = pack2(q2, q3);
            }
            s0 += __shfl_xor_sync(0xffffffffu, s0, 1);
            s0 += __shfl_xor_sync(0xffffffffu, s0, 2);
            s1 += __shfl_xor_sync(0xffffffffu, s1, 1);
            s1 += __shfl_xor_sync(0xffffffffu, s1, 2);
            l0 = l0 * co0 + s0;
            l1 = l1 * co1 + s1;
#pragma unroll
            for (int jo = 0; jo < 16; jo++) {
                cO[jo][0] *= co0; cO[jo][1] *= co0;
                cO[jo][2] *= co1; cO[jo][3] *= co1;
            }

#pragma unroll
            for (int tt = 0; tt < 4; tt++) {
                unsigned ah[4] = { pAh[2 * tt], pBh[2 * tt], pAh[2 * tt + 1], pBh[2 * tt + 1] };
                unsigned al[4] = { pAl[2 * tt], pBl[2 * tt], pAl[2 * tt + 1], pBl[2 * tt + 1] };
                unsigned baseH = (unsigned)__cvta_generic_to_shared(Vh + (tt * 16 + vrow) * AQW);
                unsigned baseL = (unsigned)__cvta_generic_to_shared(Vl + (tt * 16 + vrow) * AQW);
#pragma unroll
                for (int jo = 0; jo < 16; jo++) {
                    unsigned vh0, vh1, vl0, vl1;
                    ldsm_x2_t(vh0, vh1, baseH + jo * 16);
                    ldsm_x2_t(vl0, vl1, baseL + jo * 16);
                    unsigned bh[2] = { vh0, vh1 };
                    unsigned bl[2] = { vl0, vl1 };
                    mma_bf16(cO[jo], ah, bh);
                    mma_bf16(cO[jo], ah, bl);
                    mma_bf16(cO[jo], al, bh);
                }
            }
        }
    }

    float i0 = 1.f / l0, i1 = 1.f / l1;
#pragma unroll
    for (int jo = 0; jo < 16; jo++) {
        size_t o0 = (size_t)grow0 * DIM + h * HD + jo * 8 + 2 * c;
        *(float2*)&g_attn[o0]           = make_float2(cO[jo][0] * i0, cO[jo][1] * i0);
        *(float2*)&g_attn[o0 + 8 * DIM] = make_float2(cO[jo][2] * i1, cO[jo][3] * i1);
    }
}

// ----------------------------------------------------------------------------
// Launch. Order chosen so launch index 3 (the ncu-profiled slot) is the big
// Q-projection GEMM.
// ----------------------------------------------------------------------------
extern "C" void kernel_launch(void* const* d_in, const int* in_sizes, int n_in,
                              void* d_out, int out_size)
{
    const float* x  = (const float*)d_in[0];
    const float* wq = (const float*)d_in[1];
    const float* wk = (const float*)d_in[2];
    const float* wv = (const float*)d_in[3];
    const float* wo = (const float*)d_in[4];
    float* out = (float*)d_out;

    float *Q, *K, *V, *attn;
    __nv_bfloat16 *xsh, *xsl, *wqh, *wql, *wkh, *wkl, *wvh, *wvl, *woh, *wol;
    __nv_bfloat16 *Qhp, *Qlp, *Khp, *Klp, *Vhp, *Vlp, *ahp, *alp;
    cudaGetSymbolAddress((void**)&Q,    g_Q);
    cudaGetSymbolAddress((void**)&K,    g_K);
    cudaGetSymbolAddress((void**)&V,    g_V);
    cudaGetSymbolAddress((void**)&attn, g_attn);
    cudaGetSymbolAddress((void**)&xsh,  g_xs_h); cudaGetSymbolAddress((void**)&xsl, g_xs_l);
    cudaGetSymbolAddress((void**)&wqh,  g_wq_h); cudaGetSymbolAddress((void**)&wql, g_wq_l);
    cudaGetSymbolAddress((void**)&wkh,  g_wk_h); cudaGetSymbolAddress((void**)&wkl, g_wk_l);
    cudaGetSymbolAddress((void**)&wvh,  g_wv_h); cudaGetSymbolAddress((void**)&wvl, g_wv_l);
    cudaGetSymbolAddress((void**)&woh,  g_wo_h); cudaGetSymbolAddress((void**)&wol, g_wo_l);
    cudaGetSymbolAddress((void**)&Qhp,  g_Qh);   cudaGetSymbolAddress((void**)&Qlp, g_Ql);
    cudaGetSymbolAddress((void**)&Khp,  g_Kh);   cudaGetSymbolAddress((void**)&Klp, g_Kl);
    cudaGetSymbolAddress((void**)&Vhp,  g_Vh);   cudaGetSymbolAddress((void**)&Vlp, g_Vl);
    cudaGetSymbolAddress((void**)&ahp,  g_ah);   cudaGetSymbolAddress((void**)&alp, g_al);

    cudaFuncSetAttribute(gemm_bf16s, cudaFuncAttributeMaxDynamicSharedMemorySize,
                         GEMM_SMEM);
    cudaFuncSetAttribute(attn_tc, cudaFuncAttributeMaxDynamicSharedMemorySize,
                         ATT_SMEM_BYTES);

    const float scale = 0.08838834764831845f;  // 1/sqrt(128)

    /* 0  */ rope_table_kernel<<<SEQ * 64 / 256, 256>>>();
    /* 1  */ split_kernel<<<(SEQ * DIM / 4) / 256, 256>>>(x,  xsh, xsl, SEQ * DIM / 4);
    /* 2  */ split_kernel<<<(DIM * DIM / 4) / 256, 256>>>(wq, wqh, wql, DIM * DIM / 4);
    /* 3  */ gemm_bf16s<<<dim3(DIM / 128, SEQ / 128), 256, GEMM_SMEM>>>(xsh, xsl, wqh, wql, Q, DIM, DIM);
    /* 4  */ split_kernel<<<(KVDIM * DIM / 4) / 256, 256>>>(wk, wkh, wkl, KVDIM * DIM / 4);
    /* 5  */ gemm_bf16s<<<dim3(KVDIM / 128, SEQ / 128), 256, GEMM_SMEM>>>(xsh, xsl, wkh, wkl, K, KVDIM, DIM);
    /* 6  */ split_kernel<<<(KVDIM * DIM / 4) / 256, 256>>>(wv, wvh, wvl, KVDIM * DIM / 4);
    /* 7  */ gemm_bf16s<<<dim3(KVDIM / 128, SEQ / 128), 256, GEMM_SMEM>>>(xsh, xsl, wvh, wvl, V, KVDIM, DIM);
    /* 8  */ split_kernel<<<(DIM * DIM / 4) / 256, 256>>>(wo, woh, wol, DIM * DIM / 4);
    /* 9  */ rope_split_kernel<<<SEQ * NH  * 64 / 256, 256>>>(Q, Qhp, Qlp, NH,  DIM,   scale);
    /* 10 */ rope_split_kernel<<<SEQ * NKV * 64 / 256, 256>>>(K, Khp, Klp, NKV, KVDIM, 1.f);
    /* 11 */ split_kernel<<<(SEQ * KVDIM / 4) / 256, 256>>>(V, Vhp, Vlp, SEQ * KVDIM / 4);
    /* 12 */ attn_tc<<<dim3(SEQ / 128, NH), 256, ATT_SMEM_BYTES>>>();
    /* 13 */ split_kernel<<<(SEQ * DIM / 4) / 256, 256>>>(attn, ahp, alp, SEQ * DIM / 4);
    /* 14 */ gemm_bf16s<<<dim3(DIM / 128, SEQ / 128), 256, GEMM_SMEM>>>(ahp, alp, woh, wol, out, DIM, DIM);
}

// round 7
// speedup vs baseline: 1.2070x; 1.0450x over previous
#include <cuda_runtime.h>
#include <cuda_bf16.h>
#include <math.h>

// Problem constants
#define SEQ   2048
#define DIM   4096
#define NH    32
#define NKV   8
#define HD    128
#define KVDIM 1024   // NKV * HD

// ----------------------------------------------------------------------------
// Scratch (device-global: no allocations allowed anywhere)
// ----------------------------------------------------------------------------
__device__ float  g_Q[SEQ * DIM];
__device__ float  g_K[SEQ * KVDIM];
__device__ float  g_V[SEQ * KVDIM];
__device__ float  g_attn[SEQ * DIM];
__device__ float2 g_cs[SEQ * 64];

// bf16 split (hi/lo) scratch
__device__ __nv_bfloat16 g_xs_h[SEQ * DIM],     g_xs_l[SEQ * DIM];
__device__ __nv_bfloat16 g_wq_h[DIM * DIM],     g_wq_l[DIM * DIM];
__device__ __nv_bfloat16 g_wk_h[KVDIM * DIM],   g_wk_l[KVDIM * DIM];
__device__ __nv_bfloat16 g_wv_h[KVDIM * DIM],   g_wv_l[KVDIM * DIM];
__device__ __nv_bfloat16 g_wo_h[DIM * DIM],     g_wo_l[DIM * DIM];
__device__ __nv_bfloat16 g_Qh[SEQ * DIM],       g_Ql[SEQ * DIM];
__device__ __nv_bfloat16 g_Kh[SEQ * KVDIM],     g_Kl[SEQ * KVDIM];
__device__ __nv_bfloat16 g_Vh[SEQ * KVDIM],     g_Vl[SEQ * KVDIM];
__device__ __nv_bfloat16 g_ah[SEQ * DIM],       g_al[SEQ * DIM];

// ----------------------------------------------------------------------------
// Helpers
// ----------------------------------------------------------------------------
__device__ __forceinline__ unsigned pack2(__nv_bfloat16 a, __nv_bfloat16 b)
{
    return ((unsigned)__bfloat16_as_ushort(b) << 16) | (unsigned)__bfloat16_as_ushort(a);
}

__device__ __forceinline__ void bsplit(float x, __nv_bfloat16& h, __nv_bfloat16& l)
{
    h = __float2bfloat16(x);
    l = __float2bfloat16(x - __bfloat162float(h));
}

__device__ __forceinline__ void mma_bf16(float* c, const unsigned* a, const unsigned* b)
{
    asm volatile(
        "mma.sync.aligned.m16n8k16.row.col.f32.bf16.bf16.f32 "
        "{%0,%1,%2,%3}, {%4,%5,%6,%7}, {%8,%9}, {%0,%1,%2,%3};"
        : "+f"(c[0]), "+f"(c[1]), "+f"(c[2]), "+f"(c[3])
        : "r"(a[0]), "r"(a[1]), "r"(a[2]), "r"(a[3]), "r"(b[0]), "r"(b[1]));
}

__device__ __forceinline__ void ldsm_x2_t(unsigned& r0, unsigned& r1, unsigned addr)
{
    asm volatile("ldmatrix.sync.aligned.m8n8.x2.trans.shared.b16 {%0,%1}, [%2];"
                 : "=r"(r0), "=r"(r1) : "r"(addr));
}

__device__ __forceinline__ void ldsm_x4(unsigned& r0, unsigned& r1, unsigned& r2,
                                        unsigned& r3, unsigned addr)
{
    asm volatile("ldmatrix.sync.aligned.m8n8.x4.shared.b16 {%0,%1,%2,%3}, [%4];"
                 : "=r"(r0), "=r"(r1), "=r"(r2), "=r"(r3) : "r"(addr));
}

__device__ __forceinline__ unsigned sm32(const void* p)
{
    return (unsigned)__cvta_generic_to_shared(p);
}

#define CP_ASYNC16(dst, src) \
    asm volatile("cp.async.cg.shared.global [%0], [%1], 16;" :: "r"(dst), "l"(src))
#define CP_COMMIT() asm volatile("cp.async.commit_group;")
#define CP_WAIT(n)  asm volatile("cp.async.wait_group %0;" :: "n"(n))

// ----------------------------------------------------------------------------
// RoPE cos/sin table (double-precision angles)
// ----------------------------------------------------------------------------
__global__ void __launch_bounds__(256) rope_table_kernel()
{
    int idx = blockIdx.x * blockDim.x + threadIdx.x;
    if (idx >= SEQ * 64) return;
    int s = idx >> 6, i = idx & 63;
    double freq = exp(-(double)i / 64.0 * log(500000.0));
    double a = (double)s * freq;
    g_cs[idx] = make_float2((float)cos(a), (float)sin(a));
}

// ----------------------------------------------------------------------------
// Generic fp32 -> (bf16 hi, bf16 lo) split
// ----------------------------------------------------------------------------
__global__ void __launch_bounds__(256) split_kernel(const float* __restrict__ src,
                                                    __nv_bfloat16* __restrict__ hi,
                                                    __nv_bfloat16* __restrict__ lo,
                                                    int n4)
{
    int i = blockIdx.x * blockDim.x + threadIdx.x;
    if (i >= n4) return;
    float4 v = ((const float4*)src)[i];
    __nv_bfloat16 hx, hy, hz, hw, lx, ly, lz, lw;
    bsplit(v.x, hx, lx); bsplit(v.y, hy, ly);
    bsplit(v.z, hz, lz); bsplit(v.w, hw, lw);
    ((uint2*)hi)[i] = make_uint2(pack2(hx, hy), pack2(hz, hw));
    ((uint2*)lo)[i] = make_uint2(pack2(lx, ly), pack2(lz, lw));
}

// ----------------------------------------------------------------------------
// RoPE + optional scale + split
// ----------------------------------------------------------------------------
__global__ void __launch_bounds__(256) rope_split_kernel(const float* __restrict__ X,
                                                         __nv_bfloat16* __restrict__ hi,
                                                         __nv_bfloat16* __restrict__ lo,
                                                         int nheads, int rowstride, float scale)
{
    int idx = blockIdx.x * blockDim.x + threadIdx.x;
    int i  = idx & 63;
    int hs = idx >> 6;
    int h  = hs % nheads;
    int s  = hs / nheads;
    float2 cs = g_cs[(s << 6) + i];
    size_t off = (size_t)s * rowstride + h * HD + 2 * i;
    float2 v = *(const float2*)(X + off);
    float r0 = (v.x * cs.x - v.y * cs.y) * scale;
    float r1 = (v.x * cs.y + v.y * cs.x) * scale;
    __nv_bfloat16 h0, h1, l0, l1;
    bsplit(r0, h0, l0); bsplit(r1, h1, l1);
    *(unsigned*)(hi + off) = pack2(h0, h1);
    *(unsigned*)(lo + off) = pack2(l0, l1);
}

// ----------------------------------------------------------------------------
// Split-bf16 tensor-core GEMM v3: C[M,N] = A[M,K]*B[N,K]^T, ~fp32 accuracy.
// Block 128x128, BK=32, 3-stage cp.async pipeline, ldmatrix.x4 fragments,
// 2 CTAs/SM. ONE __syncthreads per k-tile: the top barrier of iteration kt
// already guarantees all warps finished computing on stage kt%3 before any
// warp's issue() for k-tile kt+3 overwrites it.
// ----------------------------------------------------------------------------
#define GSTRIDE 144
#define GTILEB  (128 * GSTRIDE)        // 18432 B per matrix per stage
#define GSTAGEB (2 * GTILEB)           // A + B
#define GSTAGES 3
#define GEMM_SMEM (GSTAGES * GSTAGEB)  // 110592 B

__global__ void __launch_bounds__(256, 2) gemm_bf16s(const __nv_bfloat16* __restrict__ Ahg,
                                                     const __nv_bfloat16* __restrict__ Alg,
                                                     const __nv_bfloat16* __restrict__ Bhg,
                                                     const __nv_bfloat16* __restrict__ Blg,
                                                     float* __restrict__ C, int N, int K)
{
    extern __shared__ char gsm[];
    const unsigned smem_u32 = (unsigned)__cvta_generic_to_shared(gsm);

    const int t    = threadIdx.x;
    const int lane = t & 31;
    const int wid  = t >> 5;
    const int wm   = wid & 1;
    const int wn   = wid >> 1;
    const int m0   = blockIdx.y << 7;
    const int n0   = blockIdx.x << 7;
    const int g    = lane >> 2;
    const int c    = lane & 3;

    const int arow = t >> 3;
    const int oct  = (t & 7) >> 1;
    const int part = t & 1;
    const __nv_bfloat16* srcA0 = (part ? Alg : Ahg) + (size_t)(m0 + arow) * K + oct * 8;
    const __nv_bfloat16* srcB0 = (part ? Blg : Bhg) + (size_t)(n0 + arow) * K + oct * 8;
    const unsigned dstA0 = arow * GSTRIDE + oct * 32 + part * 16;
    const unsigned dstB0 = dstA0 + GTILEB;

    const unsigned aoffs = ((wm << 6) + (lane & 7) + ((lane >> 3) & 1) * 8) * GSTRIDE
                         + (lane >> 4) * 32;
    const unsigned boffs = GTILEB
                         + ((wn << 5) + (lane & 7) + (lane >> 4) * 8) * GSTRIDE
                         + ((lane >> 3) & 1) * 32;

    float acc[4][4][4];
#pragma unroll
    for (int mt = 0; mt < 4; mt++)
#pragma unroll
        for (int nt = 0; nt < 4; nt++)
#pragma unroll
            for (int r = 0; r < 4; r++) acc[mt][nt][r] = 0.f;

    const int nkt = K >> 5;   // BK = 32

    auto issue = [&](int s, int kt) {
        const __nv_bfloat16* sa = srcA0 + kt * 32;
        const __nv_bfloat16* sb = srcB0 + kt * 32;
        unsigned da = smem_u32 + s * GSTAGEB + dstA0;
        unsigned db = smem_u32 + s * GSTAGEB + dstB0;
#pragma unroll
        for (int i = 0; i < 4; i++)
            CP_ASYNC16(da + i * 32 * GSTRIDE, sa + (size_t)i * 32 * K);
#pragma unroll
        for (int i = 0; i < 4; i++)
            CP_ASYNC16(db + i * 32 * GSTRIDE, sb + (size_t)i * 32 * K);
        CP_COMMIT();
    };

    issue(0, 0);
    if (nkt > 1) issue(1, 1);

    for (int kt = 0; kt < nkt; kt++) {
        if (kt + 1 < nkt) { CP_WAIT(1); } else { CP_WAIT(0); }
        __syncthreads();
        if (kt + 2 < nkt) issue((kt + 2) % 3, kt + 2);

        const unsigned sa = smem_u32 + (kt % 3) * GSTAGEB + aoffs;
        const unsigned sb = smem_u32 + (kt % 3) * GSTAGEB + boffs;
#pragma unroll
        for (int kh = 0; kh < 2; kh++) {
            unsigned bh[4][2], bl[4][2];
#pragma unroll
            for (int q = 0; q < 2; q++) {
                unsigned base = sb + q * (16 * GSTRIDE) + kh * 64;
                ldsm_x4(bh[2 * q][0], bh[2 * q][1], bh[2 * q + 1][0], bh[2 * q + 1][1], base);
                ldsm_x4(bl[2 * q][0], bl[2 * q][1], bl[2 * q + 1][0], bl[2 * q + 1][1], base + 16);
            }
#pragma unroll
            for (int mt = 0; mt < 4; mt++) {
                unsigned ah[4], al[4];
                unsigned base = sa + mt * (16 * GSTRIDE) + kh * 64;
                ldsm_x4(ah[0], ah[1], ah[2], ah[3], base);
                ldsm_x4(al[0], al[1], al[2], al[3], base + 16);
#pragma unroll
                for (int nt = 0; nt < 4; nt++) {
                    mma_bf16(acc[mt][nt], ah, bh[nt]);
                    mma_bf16(acc[mt][nt], ah, bl[nt]);
                    mma_bf16(acc[mt][nt], al, bh[nt]);
                }
            }
        }
        // no trailing barrier: next iteration's top barrier protects stage reuse
    }

    const int erow = m0 + (wm << 6) + g;
    const int ecol = n0 + (wn << 5) + (c << 1);
#pragma unroll
    for (int mt = 0; mt < 4; mt++) {
#pragma unroll
        for (int nt = 0; nt < 4; nt++) {
            float* p0 = C + (size_t)(erow + mt * 16) * N + ecol + nt * 8;
            float* p1 = p0 + 8 * N;
            *(float2*)p0 = make_float2(acc[mt][nt][0], acc[mt][nt][1]);
            *(float2*)p1 = make_float2(acc[mt][nt][2], acc[mt][nt][3]);
        }
    }
}

// ----------------------------------------------------------------------------
// Tensor-core flash attention v2: split-bf16 (3-MMA) math unchanged
// (validated, rel_err 7.1e-5); K/V tiles cp.async double-buffered so tile
// kt+1's global loads overlap tile kt's MMA work. One barrier per tile.
// ----------------------------------------------------------------------------
#define AQW 68
#define KVSTAGEW (4 * 64 * AQW)                 // words per stage (Kh,Kl,Vh,Vl)
#define ATT_SMEM_BYTES ((2 * 128 * AQW + 2 * KVSTAGEW) * 4)   // 208896 B

__global__ void __launch_bounds__(256) attn_tc()
{
    extern __shared__ unsigned smw[];
    unsigned* Qh = smw;
    unsigned* Ql = Qh + 128 * AQW;
    unsigned* KV0 = Ql + 128 * AQW;             // stage base; layout per stage:
                                                // [Kh|Kl|Vh|Vl] each 64*AQW words

    const int qb  = blockIdx.x;
    const int h   = blockIdx.y;
    const int kvh = h >> 2;
    const int t    = threadIdx.x;
    const int lane = t & 31;
    const int w    = t >> 5;
    const int g    = lane >> 2;
    const int c    = lane & 3;

    // Q tile load (once)
    for (int e = t; e < 2048; e += 256) {
        int r = e >> 4, u = e & 15;
        size_t go = (size_t)(qb * 128 + r) * DIM + h * HD + u * 8;
        *(uint4*)&Qh[r * AQW + u * 4] = *(const uint4*)(g_Qh + go);
        *(uint4*)&Ql[r * AQW + u * 4] = *(const uint4*)(g_Ql + go);
    }

    // cp.async K/V tile issue: 64 rows x 128 bf16 x 4 arrays per stage
    auto issue_kv = [&](int s, int kt) {
        unsigned sb = sm32(KV0 + s * KVSTAGEW);
#pragma unroll
        for (int i = 0; i < 4; i++) {
            int e = t + 256 * i;
            int r = e >> 4, u = e & 15;
            unsigned d = sb + (r * AQW + u * 4) * 4;
            size_t go = (size_t)(kt * 64 + r) * KVDIM + kvh * HD + u * 8;
            CP_ASYNC16(d,                    g_Kh + go);
            CP_ASYNC16(d + 64 * AQW * 4,     g_Kl + go);
            CP_ASYNC16(d + 2 * 64 * AQW * 4, g_Vh + go);
            CP_ASYNC16(d + 3 * 64 * AQW * 4, g_Vl + go);
        }
        CP_COMMIT();
    };

    float cO[16][4];
#pragma unroll
    for (int jo = 0; jo < 16; jo++)
#pragma unroll
        for (int r = 0; r < 4; r++) cO[jo][r] = 0.f;
    float m0 = -INFINITY, m1 = -INFINITY, l0 = 0.f, l1 = 0.f;

    const int grow0 = qb * 128 + w * 16 + g;
    const int vrow  = lane & 15;

    const int ntiles = 2 * qb + 2;
    issue_kv(0, 0);

    for (int kt = 0; kt < ntiles; kt++) {
        CP_WAIT(0);          // tile kt complete
        __syncthreads();     // visibility across warps (+ Q on iter 0)
        if (kt + 1 < ntiles) issue_kv((kt + 1) & 1, kt + 1);

        unsigned* Kh = KV0 + (kt & 1) * KVSTAGEW;
        unsigned* Kl = Kh + 64 * AQW;
        unsigned* Vh = Kl + 64 * AQW;
        unsigned* Vl = Vh + 64 * AQW;

        if (kt * 64 <= qb * 128 + w * 16 + 15) {
            float cS[8][4];
#pragma unroll
            for (int j = 0; j < 8; j++)
#pragma unroll
                for (int r = 0; r < 4; r++) cS[j][r] = 0.f;

#pragma unroll
            for (int kk = 0; kk < 8; kk++) {
                const unsigned* qpH = Qh + (w * 16 + g) * AQW + kk * 8 + c;
                const unsigned* qpL = Ql + (w * 16 + g) * AQW + kk * 8 + c;
                unsigned qah[4] = { qpH[0], qpH[8 * AQW], qpH[4], qpH[8 * AQW + 4] };
                unsigned qal[4] = { qpL[0], qpL[8 * AQW], qpL[4], qpL[8 * AQW + 4] };
#pragma unroll
                for (int j = 0; j < 8; j++) {
                    const unsigned* kpH = Kh + (j * 8 + g) * AQW + kk * 8 + c;
                    const unsigned* kpL = Kl + (j * 8 + g) * AQW + kk * 8 + c;
                    unsigned bh[2] = { kpH[0], kpH[4] };
                    unsigned bl[2] = { kpL[0], kpL[4] };
                    mma_bf16(cS[j], qah, bh);
                    mma_bf16(cS[j], qah, bl);
                    mma_bf16(cS[j], qal, bh);
                }
            }

            if (kt * 64 + 63 > grow0) {
#pragma unroll
                for (int j = 0; j < 8; j++) {
                    int col = kt * 64 + j * 8 + 2 * c;
                    if (col     > grow0)     cS[j][0] = -INFINITY;
                    if (col + 1 > grow0)     cS[j][1] = -INFINITY;
                    if (col     > grow0 + 8) cS[j][2] = -INFINITY;
                    if (col + 1 > grow0 + 8) cS[j][3] = -INFINITY;
                }
            }

            float mx0 = -INFINITY, mx1 = -INFINITY;
#pragma unroll
            for (int j = 0; j < 8; j++) {
                mx0 = fmaxf(mx0, fmaxf(cS[j][0], cS[j][1]));
                mx1 = fmaxf(mx1, fmaxf(cS[j][2], cS[j][3]));
            }
            mx0 = fmaxf(mx0, __shfl_xor_sync(0xffffffffu, mx0, 1));
            mx0 = fmaxf(mx0, __shfl_xor_sync(0xffffffffu, mx0, 2));
            mx1 = fmaxf(mx1, __shfl_xor_sync(0xffffffffu, mx1, 1));
            mx1 = fmaxf(mx1, __shfl_xor_sync(0xffffffffu, mx1, 2));
            float mn0 = fmaxf(m0, mx0), mn1 = fmaxf(m1, mx1);
            float co0 = __expf(m0 - mn0), co1 = __expf(m1 - mn1);
            m0 = mn0; m1 = mn1;

            unsigned pAh[8], pAl[8], pBh[8], pBl[8];
            float s0 = 0.f, s1 = 0.f;
#pragma unroll
            for (int j = 0; j < 8; j++) {
                float p0 = __expf(cS[j][0] - mn0);
                float p1 = __expf(cS[j][1] - mn0);
                float p2 = __expf(cS[j][2] - mn1);
                float p3 = __expf(cS[j][3] - mn1);
                s0 += p0 + p1;
                s1 += p2 + p3;
                __nv_bfloat16 h0, h1, h2, h3, q0, q1, q2, q3;
                bsplit(p0, h0, q0); bsplit(p1, h1, q1);
                bsplit(p2, h2, q2); bsplit(p3, h3, q3);
                pAh[j] = pack2(h0, h1); pAl[j] = pack2(q0, q1);
                pBh[j] = pack2(h2, h3); pBl[j] = pack2(q2, q3);
            }
            s0 += __shfl_xor_sync(0xffffffffu, s0, 1);
            s0 += __shfl_xor_sync(0xffffffffu, s0, 2);
            s1 += __shfl_xor_sync(0xffffffffu, s1, 1);
            s1 += __shfl_xor_sync(0xffffffffu, s1, 2);
            l0 = l0 * co0 + s0;
            l1 = l1 * co1 + s1;
#pragma unroll
            for (int jo = 0; jo < 16; jo++) {
                cO[jo][0] *= co0; cO[jo][1] *= co0;
                cO[jo][2] *= co1; cO[jo][3] *= co1;
            }

#pragma unroll
            for (int tt = 0; tt < 4; tt++) {
                unsigned ah[4] = { pAh[2 * tt], pBh[2 * tt], pAh[2 * tt + 1], pBh[2 * tt + 1] };
                unsigned al[4] = { pAl[2 * tt], pBl[2 * tt], pAl[2 * tt + 1], pBl[2 * tt + 1] };
                unsigned baseH = sm32(Vh + (tt * 16 + vrow) * AQW);
                unsigned baseL = sm32(Vl + (tt * 16 + vrow) * AQW);
#pragma unroll
                for (int jo = 0; jo < 16; jo++) {
                    unsigned vh0, vh1, vl0, vl1;
                    ldsm_x2_t(vh0, vh1, baseH + jo * 16);
                    ldsm_x2_t(vl0, vl1, baseL + jo * 16);
                    unsigned bh[2] = { vh0, vh1 };
                    unsigned bl[2] = { vl0, vl1 };
                    mma_bf16(cO[jo], ah, bh);
                    mma_bf16(cO[jo], ah, bl);
                    mma_bf16(cO[jo], al, bh);
                }
            }
        }
    }

    float i0 = 1.f / l0, i1 = 1.f / l1;
#pragma unroll
    for (int jo = 0; jo < 16; jo++) {
        size_t o0 = (size_t)grow0 * DIM + h * HD + jo * 8 + 2 * c;
        *(float2*)&g_attn[o0]           = make_float2(cO[jo][0] * i0, cO[jo][1] * i0);
        *(float2*)&g_attn[o0 + 8 * DIM] = make_float2(cO[jo][2] * i1, cO[jo][3] * i1);
    }
}

// ----------------------------------------------------------------------------
// Launch. Index 3 (ncu-profiled slot) = Q-projection GEMM.
// ----------------------------------------------------------------------------
extern "C" void kernel_launch(void* const* d_in, const int* in_sizes, int n_in,
                              void* d_out, int out_size)
{
    const float* x  = (const float*)d_in[0];
    const float* wq = (const float*)d_in[1];
    const float* wk = (const float*)d_in[2];
    const float* wv = (const float*)d_in[3];
    const float* wo = (const float*)d_in[4];
    float* out = (float*)d_out;

    float *Q, *K, *V, *attn;
    __nv_bfloat16 *xsh, *xsl, *wqh, *wql, *wkh, *wkl, *wvh, *wvl, *woh, *wol;
    __nv_bfloat16 *Qhp, *Qlp, *Khp, *Klp, *Vhp, *Vlp, *ahp, *alp;
    cudaGetSymbolAddress((void**)&Q,    g_Q);
    cudaGetSymbolAddress((void**)&K,    g_K);
    cudaGetSymbolAddress((void**)&V,    g_V);
    cudaGetSymbolAddress((void**)&attn, g_attn);
    cudaGetSymbolAddress((void**)&xsh,  g_xs_h); cudaGetSymbolAddress((void**)&xsl, g_xs_l);
    cudaGetSymbolAddress((void**)&wqh,  g_wq_h); cudaGetSymbolAddress((void**)&wql, g_wq_l);
    cudaGetSymbolAddress((void**)&wkh,  g_wk_h); cudaGetSymbolAddress((void**)&wkl, g_wk_l);
    cudaGetSymbolAddress((void**)&wvh,  g_wv_h); cudaGetSymbolAddress((void**)&wvl, g_wv_l);
    cudaGetSymbolAddress((void**)&woh,  g_wo_h); cudaGetSymbolAddress((void**)&wol, g_wo_l);
    cudaGetSymbolAddress((void**)&Qhp,  g_Qh);   cudaGetSymbolAddress((void**)&Qlp, g_Ql);
    cudaGetSymbolAddress((void**)&Khp,  g_Kh);   cudaGetSymbolAddress((void**)&Klp, g_Kl);
    cudaGetSymbolAddress((void**)&Vhp,  g_Vh);   cudaGetSymbolAddress((void**)&Vlp, g_Vl);
    cudaGetSymbolAddress((void**)&ahp,  g_ah);   cudaGetSymbolAddress((void**)&alp, g_al);

    cudaFuncSetAttribute(gemm_bf16s, cudaFuncAttributeMaxDynamicSharedMemorySize,
                         GEMM_SMEM);
    cudaFuncSetAttribute(attn_tc, cudaFuncAttributeMaxDynamicSharedMemorySize,
                         ATT_SMEM_BYTES);

    const float scale = 0.08838834764831845f;  // 1/sqrt(128)

    /* 0  */ rope_table_kernel<<<SEQ * 64 / 256, 256>>>();
    /* 1  */ split_kernel<<<(SEQ * DIM / 4) / 256, 256>>>(x,  xsh, xsl, SEQ * DIM / 4);
    /* 2  */ split_kernel<<<(DIM * DIM / 4) / 256, 256>>>(wq, wqh, wql, DIM * DIM / 4);
    /* 3  */ gemm_bf16s<<<dim3(DIM / 128, SEQ / 128), 256, GEMM_SMEM>>>(xsh, xsl, wqh, wql, Q, DIM, DIM);
    /* 4  */ split_kernel<<<(KVDIM * DIM / 4) / 256, 256>>>(wk, wkh, wkl, KVDIM * DIM / 4);
    /* 5  */ gemm_bf16s<<<dim3(KVDIM / 128, SEQ / 128), 256, GEMM_SMEM>>>(xsh, xsl, wkh, wkl, K, KVDIM, DIM);
    /* 6  */ split_kernel<<<(KVDIM * DIM / 4) / 256, 256>>>(wv, wvh, wvl, KVDIM * DIM / 4);
    /* 7  */ gemm_bf16s<<<dim3(KVDIM / 128, SEQ / 128), 256, GEMM_SMEM>>>(xsh, xsl, wvh, wvl, V, KVDIM, DIM);
    /* 8  */ split_kernel<<<(DIM * DIM / 4) / 256, 256>>>(wo, woh, wol, DIM * DIM / 4);
    /* 9  */ rope_split_kernel<<<SEQ * NH  * 64 / 256, 256>>>(Q, Qhp, Qlp, NH,  DIM,   scale);
    /* 10 */ rope_split_kernel<<<SEQ * NKV * 64 / 256, 256>>>(K, Khp, Klp, NKV, KVDIM, 1.f);
    /* 11 */ split_kernel<<<(SEQ * KVDIM / 4) / 256, 256>>>(V, Vhp, Vlp, SEQ * KVDIM / 4);
    /* 12 */ attn_tc<<<dim3(SEQ / 128, NH), 256, ATT_SMEM_BYTES>>>();
    /* 13 */ split_kernel<<<(SEQ * DIM / 4) / 256, 256>>>(attn, ahp, alp, SEQ * DIM / 4);
    /* 14 */ gemm_bf16s<<<dim3(DIM / 128, SEQ / 128), 256, GEMM_SMEM>>>(ahp, alp, woh, wol, out, DIM, DIM);
}

// round 8
// speedup vs baseline: 1.2478x; 1.0338x over previous
#include <cuda_runtime.h>
#include <cuda_bf16.h>
#include <math.h>

// Problem constants
#define SEQ   2048
#define DIM   4096
#define NH    32
#define NKV   8
#define HD    128
#define KVDIM 1024   // NKV * HD

// ----------------------------------------------------------------------------
// Scratch (device-global: no allocations allowed anywhere)
// ----------------------------------------------------------------------------
__device__ float  g_Q[SEQ * DIM];
__device__ float  g_K[SEQ * KVDIM];
__device__ float  g_V[SEQ * KVDIM];
__device__ float  g_attn[SEQ * DIM];
__device__ float2 g_cs[SEQ * 64];

// bf16 split (hi/lo) scratch
__device__ __nv_bfloat16 g_xs_h[SEQ * DIM],     g_xs_l[SEQ * DIM];
__device__ __nv_bfloat16 g_wq_h[DIM * DIM],     g_wq_l[DIM * DIM];
__device__ __nv_bfloat16 g_wk_h[KVDIM * DIM],   g_wk_l[KVDIM * DIM];
__device__ __nv_bfloat16 g_wv_h[KVDIM * DIM],   g_wv_l[KVDIM * DIM];
__device__ __nv_bfloat16 g_wo_h[DIM * DIM],     g_wo_l[DIM * DIM];
__device__ __nv_bfloat16 g_Qh[SEQ * DIM],       g_Ql[SEQ * DIM];
__device__ __nv_bfloat16 g_Kh[SEQ * KVDIM],     g_Kl[SEQ * KVDIM];
__device__ __nv_bfloat16 g_Vh[SEQ * KVDIM],     g_Vl[SEQ * KVDIM];
__device__ __nv_bfloat16 g_ah[SEQ * DIM],       g_al[SEQ * DIM];

// ----------------------------------------------------------------------------
// Helpers
// ----------------------------------------------------------------------------
__device__ __forceinline__ unsigned pack2(__nv_bfloat16 a, __nv_bfloat16 b)
{
    return ((unsigned)__bfloat16_as_ushort(b) << 16) | (unsigned)__bfloat16_as_ushort(a);
}

__device__ __forceinline__ void bsplit(float x, __nv_bfloat16& h, __nv_bfloat16& l)
{
    h = __float2bfloat16(x);
    l = __float2bfloat16(x - __bfloat162float(h));
}

__device__ __forceinline__ void mma_bf16(float* c, const unsigned* a, const unsigned* b)
{
    asm volatile(
        "mma.sync.aligned.m16n8k16.row.col.f32.bf16.bf16.f32 "
        "{%0,%1,%2,%3}, {%4,%5,%6,%7}, {%8,%9}, {%0,%1,%2,%3};"
        : "+f"(c[0]), "+f"(c[1]), "+f"(c[2]), "+f"(c[3])
        : "r"(a[0]), "r"(a[1]), "r"(a[2]), "r"(a[3]), "r"(b[0]), "r"(b[1]));
}

__device__ __forceinline__ void ldsm_x2_t(unsigned& r0, unsigned& r1, unsigned addr)
{
    asm volatile("ldmatrix.sync.aligned.m8n8.x2.trans.shared.b16 {%0,%1}, [%2];"
                 : "=r"(r0), "=r"(r1) : "r"(addr));
}

__device__ __forceinline__ void ldsm_x4(unsigned& r0, unsigned& r1, unsigned& r2,
                                        unsigned& r3, unsigned addr)
{
    asm volatile("ldmatrix.sync.aligned.m8n8.x4.shared.b16 {%0,%1,%2,%3}, [%4];"
                 : "=r"(r0), "=r"(r1), "=r"(r2), "=r"(r3) : "r"(addr));
}

__device__ __forceinline__ unsigned sm32(const void* p)
{
    return (unsigned)__cvta_generic_to_shared(p);
}

#define CP_ASYNC16(dst, src) \
    asm volatile("cp.async.cg.shared.global [%0], [%1], 16;" :: "r"(dst), "l"(src))
#define CP_COMMIT() asm volatile("cp.async.commit_group;")
#define CP_WAIT(n)  asm volatile("cp.async.wait_group %0;" :: "n"(n))

// ----------------------------------------------------------------------------
// RoPE cos/sin table (double-precision angles)
// ----------------------------------------------------------------------------
__global__ void __launch_bounds__(256) rope_table_kernel()
{
    int idx = blockIdx.x * blockDim.x + threadIdx.x;
    if (idx >= SEQ * 64) return;
    int s = idx >> 6, i = idx & 63;
    double freq = exp(-(double)i / 64.0 * log(500000.0));
    double a = (double)s * freq;
    g_cs[idx] = make_float2((float)cos(a), (float)sin(a));
}

// ----------------------------------------------------------------------------
// fp32 -> (bf16 hi, bf16 lo) split; one- and two-source variants
// ----------------------------------------------------------------------------
__device__ __forceinline__ void split_one(const float* src, __nv_bfloat16* hi,
                                          __nv_bfloat16* lo, int i)
{
    float4 v = ((const float4*)src)[i];
    __nv_bfloat16 hx, hy, hz, hw, lx, ly, lz, lw;
    bsplit(v.x, hx, lx); bsplit(v.y, hy, ly);
    bsplit(v.z, hz, lz); bsplit(v.w, hw, lw);
    ((uint2*)hi)[i] = make_uint2(pack2(hx, hy), pack2(hz, hw));
    ((uint2*)lo)[i] = make_uint2(pack2(lx, ly), pack2(lz, lw));
}

__global__ void __launch_bounds__(256) split_kernel(const float* __restrict__ src,
                                                    __nv_bfloat16* __restrict__ hi,
                                                    __nv_bfloat16* __restrict__ lo,
                                                    int n4)
{
    int i = blockIdx.x * blockDim.x + threadIdx.x;
    if (i >= n4) return;
    split_one(src, hi, lo, i);
}

__global__ void __launch_bounds__(256) split2_kernel(const float* __restrict__ s1,
                                                     __nv_bfloat16* __restrict__ h1,
                                                     __nv_bfloat16* __restrict__ l1,
                                                     int n41,
                                                     const float* __restrict__ s2,
                                                     __nv_bfloat16* __restrict__ h2,
                                                     __nv_bfloat16* __restrict__ l2,
                                                     int n42)
{
    int i = blockIdx.x * blockDim.x + threadIdx.x;
    if (i < n41) split_one(s1, h1, l1, i);
    else if (i - n41 < n42) split_one(s2, h2, l2, i - n41);
}

// ----------------------------------------------------------------------------
// RoPE + optional scale + split
// ----------------------------------------------------------------------------
__global__ void __launch_bounds__(256) rope_split_kernel(const float* __restrict__ X,
                                                         __nv_bfloat16* __restrict__ hi,
                                                         __nv_bfloat16* __restrict__ lo,
                                                         int nheads, int rowstride, float scale)
{
    int idx = blockIdx.x * blockDim.x + threadIdx.x;
    int i  = idx & 63;
    int hs = idx >> 6;
    int h  = hs % nheads;
    int s  = hs / nheads;
    float2 cs = g_cs[(s << 6) + i];
    size_t off = (size_t)s * rowstride + h * HD + 2 * i;
    float2 v = *(const float2*)(X + off);
    float r0 = (v.x * cs.x - v.y * cs.y) * scale;
    float r1 = (v.x * cs.y + v.y * cs.x) * scale;
    __nv_bfloat16 h0, h1, l0, l1;
    bsplit(r0, h0, l0); bsplit(r1, h1, l1);
    *(unsigned*)(hi + off) = pack2(h0, h1);
    *(unsigned*)(lo + off) = pack2(l0, l1);
}

// ----------------------------------------------------------------------------
// Split-bf16 tensor-core GEMM core (v4): block 128x128, BK=32, 3-stage
// cp.async, ldmatrix.x4, one barrier/ktile. MMA issue order: term-by-term
// across the 4 nt accumulators (RAW distance 4) — per-accumulator FP order
// unchanged vs v3 (hh, hl, lh), so results are bit-identical.
// ----------------------------------------------------------------------------
#define GSTRIDE 144
#define GTILEB  (128 * GSTRIDE)
#define GSTAGEB (2 * GTILEB)
#define GSTAGES 3
#define GEMM_SMEM (GSTAGES * GSTAGEB)  // 110592 B

__device__ __forceinline__ void gemm_core(const __nv_bfloat16* Ahg, const __nv_bfloat16* Alg,
                                          const __nv_bfloat16* Bhg, const __nv_bfloat16* Blg,
                                          float* C, int m0, int n0, int N, int K,
                                          char* gsm)
{
    const unsigned smem_u32 = (unsigned)__cvta_generic_to_shared(gsm);

    const int t    = threadIdx.x;
    const int lane = t & 31;
    const int wid  = t >> 5;
    const int wm   = wid & 1;
    const int wn   = wid >> 1;
    const int g    = lane >> 2;
    const int c    = lane & 3;

    const int arow = t >> 3;
    const int oct  = (t & 7) >> 1;
    const int part = t & 1;
    const __nv_bfloat16* srcA0 = (part ? Alg : Ahg) + (size_t)(m0 + arow) * K + oct * 8;
    const __nv_bfloat16* srcB0 = (part ? Blg : Bhg) + (size_t)(n0 + arow) * K + oct * 8;
    const unsigned dstA0 = arow * GSTRIDE + oct * 32 + part * 16;
    const unsigned dstB0 = dstA0 + GTILEB;

    const unsigned aoffs = ((wm << 6) + (lane & 7) + ((lane >> 3) & 1) * 8) * GSTRIDE
                         + (lane >> 4) * 32;
    const unsigned boffs = GTILEB
                         + ((wn << 5) + (lane & 7) + (lane >> 4) * 8) * GSTRIDE
                         + ((lane >> 3) & 1) * 32;

    float acc[4][4][4];
#pragma unroll
    for (int mt = 0; mt < 4; mt++)
#pragma unroll
        for (int nt = 0; nt < 4; nt++)
#pragma unroll
            for (int r = 0; r < 4; r++) acc[mt][nt][r] = 0.f;

    const int nkt = K >> 5;

    auto issue = [&](int s, int kt) {
        const __nv_bfloat16* sa = srcA0 + kt * 32;
        const __nv_bfloat16* sb = srcB0 + kt * 32;
        unsigned da = smem_u32 + s * GSTAGEB + dstA0;
        unsigned db = smem_u32 + s * GSTAGEB + dstB0;
#pragma unroll
        for (int i = 0; i < 4; i++)
            CP_ASYNC16(da + i * 32 * GSTRIDE, sa + (size_t)i * 32 * K);
#pragma unroll
        for (int i = 0; i < 4; i++)
            CP_ASYNC16(db + i * 32 * GSTRIDE, sb + (size_t)i * 32 * K);
        CP_COMMIT();
    };

    issue(0, 0);
    if (nkt > 1) issue(1, 1);

    for (int kt = 0; kt < nkt; kt++) {
        if (kt + 1 < nkt) { CP_WAIT(1); } else { CP_WAIT(0); }
        __syncthreads();
        if (kt + 2 < nkt) issue((kt + 2) % 3, kt + 2);

        const unsigned sa = smem_u32 + (kt % 3) * GSTAGEB + aoffs;
        const unsigned sb = smem_u32 + (kt % 3) * GSTAGEB + boffs;
#pragma unroll
        for (int kh = 0; kh < 2; kh++) {
            unsigned bh[4][2], bl[4][2];
#pragma unroll
            for (int q = 0; q < 2; q++) {
                unsigned base = sb + q * (16 * GSTRIDE) + kh * 64;
                ldsm_x4(bh[2 * q][0], bh[2 * q][1], bh[2 * q + 1][0], bh[2 * q + 1][1], base);
                ldsm_x4(bl[2 * q][0], bl[2 * q][1], bl[2 * q + 1][0], bl[2 * q + 1][1], base + 16);
            }
#pragma unroll
            for (int mt = 0; mt < 4; mt++) {
                unsigned ah[4], al[4];
                unsigned base = sa + mt * (16 * GSTRIDE) + kh * 64;
                ldsm_x4(ah[0], ah[1], ah[2], ah[3], base);
                ldsm_x4(al[0], al[1], al[2], al[3], base + 16);
                // term-by-term: consecutive MMAs hit different accumulators
#pragma unroll
                for (int nt = 0; nt < 4; nt++) mma_bf16(acc[mt][nt], ah, bh[nt]);
#pragma unroll
                for (int nt = 0; nt < 4; nt++) mma_bf16(acc[mt][nt], ah, bl[nt]);
#pragma unroll
                for (int nt = 0; nt < 4; nt++) mma_bf16(acc[mt][nt], al, bh[nt]);
            }
        }
    }

    const int erow = m0 + (wm << 6) + g;
    const int ecol = n0 + (wn << 5) + (c << 1);
#pragma unroll
    for (int mt = 0; mt < 4; mt++) {
#pragma unroll
        for (int nt = 0; nt < 4; nt++) {
            float* p0 = C + (size_t)(erow + mt * 16) * N + ecol + nt * 8;
            float* p1 = p0 + 8 * N;
            *(float2*)p0 = make_float2(acc[mt][nt][0], acc[mt][nt][1]);
            *(float2*)p1 = make_float2(acc[mt][nt][2], acc[mt][nt][3]);
        }
    }
}

// Plain GEMM (used for the O projection)
__global__ void __launch_bounds__(256, 2) gemm_bf16s(const __nv_bfloat16* __restrict__ Ahg,
                                                     const __nv_bfloat16* __restrict__ Alg,
                                                     const __nv_bfloat16* __restrict__ Bhg,
                                                     const __nv_bfloat16* __restrict__ Blg,
                                                     float* __restrict__ C, int N, int K)
{
    extern __shared__ char gsm[];
    gemm_core(Ahg, Alg, Bhg, Blg, C, blockIdx.y << 7, blockIdx.x << 7, N, K, gsm);
}

// Fused Q/K/V projection GEMM: one grid (48 x 16) covering all three outputs
// for full-wave occupancy. blockIdx.x selects the weight/output region.
__global__ void __launch_bounds__(256, 2) gemm_qkv(const __nv_bfloat16* __restrict__ xsh,
                                                   const __nv_bfloat16* __restrict__ xsl,
                                                   const __nv_bfloat16* __restrict__ wqh,
                                                   const __nv_bfloat16* __restrict__ wql,
                                                   const __nv_bfloat16* __restrict__ wkh,
                                                   const __nv_bfloat16* __restrict__ wkl,
                                                   const __nv_bfloat16* __restrict__ wvh,
                                                   const __nv_bfloat16* __restrict__ wvl,
                                                   float* __restrict__ Q,
                                                   float* __restrict__ K,
                                                   float* __restrict__ V)
{
    extern __shared__ char gsm[];
    const int bx = blockIdx.x;
    const __nv_bfloat16 *Bh, *Bl;
    float* C;
    int Nout, n0;
    if (bx < 32)      { Bh = wqh; Bl = wql; C = Q; Nout = DIM;   n0 = bx * 128; }
    else if (bx < 40) { Bh = wkh; Bl = wkl; C = K; Nout = KVDIM; n0 = (bx - 32) * 128; }
    else              { Bh = wvh; Bl = wvl; C = V; Nout = KVDIM; n0 = (bx - 40) * 128; }
    gemm_core(xsh, xsl, Bh, Bl, C, blockIdx.y << 7, n0, Nout, DIM, gsm);
}

// ----------------------------------------------------------------------------
// Tensor-core flash attention v3: split-bf16 math unchanged; K/V cp.async
// double-buffered; MMA chains broken up (pairs, per-acc order preserved).
// ----------------------------------------------------------------------------
#define AQW 68
#define KVSTAGEW (4 * 64 * AQW)
#define ATT_SMEM_BYTES ((2 * 128 * AQW + 2 * KVSTAGEW) * 4)   // 208896 B

__global__ void __launch_bounds__(256) attn_tc()
{
    extern __shared__ unsigned smw[];
    unsigned* Qh = smw;
    unsigned* Ql = Qh + 128 * AQW;
    unsigned* KV0 = Ql + 128 * AQW;

    const int qb  = blockIdx.x;
    const int h   = blockIdx.y;
    const int kvh = h >> 2;
    const int t    = threadIdx.x;
    const int lane = t & 31;
    const int w    = t >> 5;
    const int g    = lane >> 2;
    const int c    = lane & 3;

    for (int e = t; e < 2048; e += 256) {
        int r = e >> 4, u = e & 15;
        size_t go = (size_t)(qb * 128 + r) * DIM + h * HD + u * 8;
        *(uint4*)&Qh[r * AQW + u * 4] = *(const uint4*)(g_Qh + go);
        *(uint4*)&Ql[r * AQW + u * 4] = *(const uint4*)(g_Ql + go);
    }

    auto issue_kv = [&](int s, int kt) {
        unsigned sb = sm32(KV0 + s * KVSTAGEW);
#pragma unroll
        for (int i = 0; i < 4; i++) {
            int e = t + 256 * i;
            int r = e >> 4, u = e & 15;
            unsigned d = sb + (r * AQW + u * 4) * 4;
            size_t go = (size_t)(kt * 64 + r) * KVDIM + kvh * HD + u * 8;
            CP_ASYNC16(d,                    g_Kh + go);
            CP_ASYNC16(d + 64 * AQW * 4,     g_Kl + go);
            CP_ASYNC16(d + 2 * 64 * AQW * 4, g_Vh + go);
            CP_ASYNC16(d + 3 * 64 * AQW * 4, g_Vl + go);
        }
        CP_COMMIT();
    };

    float cO[16][4];
#pragma unroll
    for (int jo = 0; jo < 16; jo++)
#pragma unroll
        for (int r = 0; r < 4; r++) cO[jo][r] = 0.f;
    float m0 = -INFINITY, m1 = -INFINITY, l0 = 0.f, l1 = 0.f;

    const int grow0 = qb * 128 + w * 16 + g;
    const int vrow  = lane & 15;

    const int ntiles = 2 * qb + 2;
    issue_kv(0, 0);

    for (int kt = 0; kt < ntiles; kt++) {
        CP_WAIT(0);
        __syncthreads();
        if (kt + 1 < ntiles) issue_kv((kt + 1) & 1, kt + 1);

        unsigned* Kh = KV0 + (kt & 1) * KVSTAGEW;
        unsigned* Kl = Kh + 64 * AQW;
        unsigned* Vh = Kl + 64 * AQW;
        unsigned* Vl = Vh + 64 * AQW;

        if (kt * 64 <= qb * 128 + w * 16 + 15) {
            float cS[8][4];
#pragma unroll
            for (int j = 0; j < 8; j++)
#pragma unroll
                for (int r = 0; r < 4; r++) cS[j][r] = 0.f;

#pragma unroll
            for (int kk = 0; kk < 8; kk++) {
                const unsigned* qpH = Qh + (w * 16 + g) * AQW + kk * 8 + c;
                const unsigned* qpL = Ql + (w * 16 + g) * AQW + kk * 8 + c;
                unsigned qah[4] = { qpH[0], qpH[8 * AQW], qpH[4], qpH[8 * AQW + 4] };
                unsigned qal[4] = { qpL[0], qpL[8 * AQW], qpL[4], qpL[8 * AQW + 4] };
                // pairs of j: consecutive MMAs alternate accumulators
#pragma unroll
                for (int j = 0; j < 8; j += 2) {
                    const unsigned* kpH0 = Kh + (j * 8 + g) * AQW + kk * 8 + c;
                    const unsigned* kpL0 = Kl + (j * 8 + g) * AQW + kk * 8 + c;
                    const unsigned* kpH1 = kpH0 + 8 * AQW;
                    const unsigned* kpL1 = kpL0 + 8 * AQW;
                    unsigned bh0[2] = { kpH0[0], kpH0[4] };
                    unsigned bl0[2] = { kpL0[0], kpL0[4] };
                    unsigned bh1[2] = { kpH1[0], kpH1[4] };
                    unsigned bl1[2] = { kpL1[0], kpL1[4] };
                    mma_bf16(cS[j],     qah, bh0);
                    mma_bf16(cS[j + 1], qah, bh1);
                    mma_bf16(cS[j],     qah, bl0);
                    mma_bf16(cS[j + 1], qah, bl1);
                    mma_bf16(cS[j],     qal, bh0);
                    mma_bf16(cS[j + 1], qal, bh1);
                }
            }

            if (kt * 64 + 63 > grow0) {
#pragma unroll
                for (int j = 0; j < 8; j++) {
                    int col = kt * 64 + j * 8 + 2 * c;
                    if (col     > grow0)     cS[j][0] = -INFINITY;
                    if (col + 1 > grow0)     cS[j][1] = -INFINITY;
                    if (col     > grow0 + 8) cS[j][2] = -INFINITY;
                    if (col + 1 > grow0 + 8) cS[j][3] = -INFINITY;
                }
            }

            float mx0 = -INFINITY, mx1 = -INFINITY;
#pragma unroll
            for (int j = 0; j < 8; j++) {
                mx0 = fmaxf(mx0, fmaxf(cS[j][0], cS[j][1]));
                mx1 = fmaxf(mx1, fmaxf(cS[j][2], cS[j][3]));
            }
            mx0 = fmaxf(mx0, __shfl_xor_sync(0xffffffffu, mx0, 1));
            mx0 = fmaxf(mx0, __shfl_xor_sync(0xffffffffu, mx0, 2));
            mx1 = fmaxf(mx1, __shfl_xor_sync(0xffffffffu, mx1, 1));
            mx1 = fmaxf(mx1, __shfl_xor_sync(0xffffffffu, mx1, 2));
            float mn0 = fmaxf(m0, mx0), mn1 = fmaxf(m1, mx1);
            float co0 = __expf(m0 - mn0), co1 = __expf(m1 - mn1);
            m0 = mn0; m1 = mn1;

            unsigned pAh[8], pAl[8], pBh[8], pBl[8];
            float s0 = 0.f, s1 = 0.f;
#pragma unroll
            for (int j = 0; j < 8; j++) {
                float p0 = __expf(cS[j][0] - mn0);
                float p1 = __expf(cS[j][1] - mn0);
                float p2 = __expf(cS[j][2] - mn1);
                float p3 = __expf(cS[j][3] - mn1);
                s0 += p0 + p1;
                s1 += p2 + p3;
                __nv_bfloat16 h0, h1, h2, h3, q0, q1, q2, q3;
                bsplit(p0, h0, q0); bsplit(p1, h1, q1);
                bsplit(p2, h2, q2); bsplit(p3, h3, q3);
                pAh[j] = pack2(h0, h1); pAl[j] = pack2(q0, q1);
                pBh[j] = pack2(h2, h3); pBl[j] = pack2(q2, q3);
            }
            s0 += __shfl_xor_sync(0xffffffffu, s0, 1);
            s0 += __shfl_xor_sync(0xffffffffu, s0, 2);
            s1 += __shfl_xor_sync(0xffffffffu, s1, 1);
            s1 += __shfl_xor_sync(0xffffffffu, s1, 2);
            l0 = l0 * co0 + s0;
            l1 = l1 * co1 + s1;
#pragma unroll
            for (int jo = 0; jo < 16; jo++) {
                cO[jo][0] *= co0; cO[jo][1] *= co0;
                cO[jo][2] *= co1; cO[jo][3] *= co1;
            }

#pragma unroll
            for (int tt = 0; tt < 4; tt++) {
                unsigned ah[4] = { pAh[2 * tt], pBh[2 * tt], pAh[2 * tt + 1], pBh[2 * tt + 1] };
                unsigned al[4] = { pAl[2 * tt], pBl[2 * tt], pAl[2 * tt + 1], pBl[2 * tt + 1] };
                unsigned baseH = sm32(Vh + (tt * 16 + vrow) * AQW);
                unsigned baseL = sm32(Vl + (tt * 16 + vrow) * AQW);
                // pairs of jo: consecutive MMAs alternate accumulators
#pragma unroll
                for (int jo = 0; jo < 16; jo += 2) {
                    unsigned h00, h01, l00, l01, h10, h11, l10, l11;
                    ldsm_x2_t(h00, h01, baseH + jo * 16);
                    ldsm_x2_t(l00, l01, baseL + jo * 16);
                    ldsm_x2_t(h10, h11, baseH + jo * 16 + 16);
                    ldsm_x2_t(l10, l11, baseL + jo * 16 + 16);
                    unsigned bh0[2] = { h00, h01 }, bl0[2] = { l00, l01 };
                    unsigned bh1[2] = { h10, h11 }, bl1[2] = { l10, l11 };
                    mma_bf16(cO[jo],     ah, bh0);
                    mma_bf16(cO[jo + 1], ah, bh1);
                    mma_bf16(cO[jo],     ah, bl0);
                    mma_bf16(cO[jo + 1], ah, bl1);
                    mma_bf16(cO[jo],     al, bh0);
                    mma_bf16(cO[jo + 1], al, bh1);
                }
            }
        }
    }

    float i0 = 1.f / l0, i1 = 1.f / l1;
#pragma unroll
    for (int jo = 0; jo < 16; jo++) {
        size_t o0 = (size_t)grow0 * DIM + h * HD + jo * 8 + 2 * c;
        *(float2*)&g_attn[o0]           = make_float2(cO[jo][0] * i0, cO[jo][1] * i0);
        *(float2*)&g_attn[o0 + 8 * DIM] = make_float2(cO[jo][2] * i1, cO[jo][3] * i1);
    }
}

// ----------------------------------------------------------------------------
// Launch. Index 3 (ncu-profiled slot) = fused QKV GEMM.
// ----------------------------------------------------------------------------
extern "C" void kernel_launch(void* const* d_in, const int* in_sizes, int n_in,
                              void* d_out, int out_size)
{
    const float* x  = (const float*)d_in[0];
    const float* wq = (const float*)d_in[1];
    const float* wk = (const float*)d_in[2];
    const float* wv = (const float*)d_in[3];
    const float* wo = (const float*)d_in[4];
    float* out = (float*)d_out;

    float *Q, *K, *V, *attn;
    __nv_bfloat16 *xsh, *xsl, *wqh, *wql, *wkh, *wkl, *wvh, *wvl, *woh, *wol;
    __nv_bfloat16 *Qhp, *Qlp, *Khp, *Klp, *Vhp, *Vlp, *ahp, *alp;
    cudaGetSymbolAddress((void**)&Q,    g_Q);
    cudaGetSymbolAddress((void**)&K,    g_K);
    cudaGetSymbolAddress((void**)&V,    g_V);
    cudaGetSymbolAddress((void**)&attn, g_attn);
    cudaGetSymbolAddress((void**)&xsh,  g_xs_h); cudaGetSymbolAddress((void**)&xsl, g_xs_l);
    cudaGetSymbolAddress((void**)&wqh,  g_wq_h); cudaGetSymbolAddress((void**)&wql, g_wq_l);
    cudaGetSymbolAddress((void**)&wkh,  g_wk_h); cudaGetSymbolAddress((void**)&wkl, g_wk_l);
    cudaGetSymbolAddress((void**)&wvh,  g_wv_h); cudaGetSymbolAddress((void**)&wvl, g_wv_l);
    cudaGetSymbolAddress((void**)&woh,  g_wo_h); cudaGetSymbolAddress((void**)&wol, g_wo_l);
    cudaGetSymbolAddress((void**)&Qhp,  g_Qh);   cudaGetSymbolAddress((void**)&Qlp, g_Ql);
    cudaGetSymbolAddress((void**)&Khp,  g_Kh);   cudaGetSymbolAddress((void**)&Klp, g_Kl);
    cudaGetSymbolAddress((void**)&Vhp,  g_Vh);   cudaGetSymbolAddress((void**)&Vlp, g_Vl);
    cudaGetSymbolAddress((void**)&ahp,  g_ah);   cudaGetSymbolAddress((void**)&alp, g_al);

    cudaFuncSetAttribute(gemm_bf16s, cudaFuncAttributeMaxDynamicSharedMemorySize, GEMM_SMEM);
    cudaFuncSetAttribute(gemm_qkv,   cudaFuncAttributeMaxDynamicSharedMemorySize, GEMM_SMEM);
    cudaFuncSetAttribute(attn_tc,    cudaFuncAttributeMaxDynamicSharedMemorySize, ATT_SMEM_BYTES);

    const float scale = 0.08838834764831845f;  // 1/sqrt(128)

    const int n4x  = SEQ * DIM / 4;
    const int n4q  = DIM * DIM / 4;
    const int n4kv = KVDIM * DIM / 4;

    /* 0 */ split2_kernel<<<(n4x + n4q + 255) / 256, 256>>>(x, xsh, xsl, n4x,
                                                            wq, wqh, wql, n4q);
    /* 1 */ split2_kernel<<<(2 * n4kv + 255) / 256, 256>>>(wk, wkh, wkl, n4kv,
                                                           wv, wvh, wvl, n4kv);
    /* 2 */ rope_table_kernel<<<SEQ * 64 / 256, 256>>>();
    /* 3 */ gemm_qkv<<<dim3(48, SEQ / 128), 256, GEMM_SMEM>>>(xsh, xsl, wqh, wql,
                                                              wkh, wkl, wvh, wvl,
                                                              Q, K, V);
    /* 4 */ split_kernel<<<(n4q + 255) / 256, 256>>>(wo, woh, wol, n4q);
    /* 5 */ rope_split_kernel<<<SEQ * NH  * 64 / 256, 256>>>(Q, Qhp, Qlp, NH,  DIM,   scale);
    /* 6 */ rope_split_kernel<<<SEQ * NKV * 64 / 256, 256>>>(K, Khp, Klp, NKV, KVDIM, 1.f);
    /* 7 */ split_kernel<<<(SEQ * KVDIM / 4 + 255) / 256, 256>>>(V, Vhp, Vlp, SEQ * KVDIM / 4);
    /* 8 */ attn_tc<<<dim3(SEQ / 128, NH), 256, ATT_SMEM_BYTES>>>();
    /* 9 */ split_kernel<<<(n4x + 255) / 256, 256>>>(attn, ahp, alp, n4x);
    /* 10*/ gemm_bf16s<<<dim3(DIM / 128, SEQ / 128), 256, GEMM_SMEM>>>(ahp, alp, woh, wol, out, DIM, DIM);
}